// round 1
// baseline (speedup 1.0000x reference)
#include <cuda_runtime.h>
#include <math.h>

#define BNUM 2
#define NSEQ 2048
#define DIMD 256
#define NHEAD 8
#define HD 32
#define FFD 1024
#define ROWS (BNUM*NSEQ)   // 4096

// ---------------- scratch (device globals, no allocation) ----------------
__device__ float g_h [ROWS*DIMD];
__device__ float g_q [BNUM*NHEAD*NSEQ*HD];
__device__ float g_k [BNUM*NHEAD*NSEQ*HD];
__device__ float g_v [BNUM*NHEAD*NSEQ*HD];
__device__ float g_ao[ROWS*DIMD];
__device__ float g_x1[ROWS*DIMD];
__device__ float g_h2[ROWS*DIMD];
__device__ float g_mid[ROWS*FFD];

// ---------------- LayerNorm: one block per row of 256 ----------------
__global__ void ln_kernel(const float* __restrict__ x,
                          const float* __restrict__ g,
                          const float* __restrict__ b,
                          float* __restrict__ y)
{
    int row = blockIdx.x;
    int t   = threadIdx.x;
    const float* xr = x + (size_t)row * DIMD;
    float v = xr[t];

    __shared__ float red[8];
    __shared__ float stat[2];

    // mean
    float s = v;
    #pragma unroll
    for (int o = 16; o > 0; o >>= 1) s += __shfl_xor_sync(0xffffffffu, s, o);
    if ((t & 31) == 0) red[t >> 5] = s;
    __syncthreads();
    if (t < 32) {
        float r = (t < 8) ? red[t] : 0.f;
        #pragma unroll
        for (int o = 4; o > 0; o >>= 1) r += __shfl_xor_sync(0xffffffffu, r, o);
        if (t == 0) stat[0] = r * (1.0f / DIMD);
    }
    __syncthreads();
    float mu = stat[0];
    float d  = v - mu;

    // var
    float s2 = d * d;
    #pragma unroll
    for (int o = 16; o > 0; o >>= 1) s2 += __shfl_xor_sync(0xffffffffu, s2, o);
    if ((t & 31) == 0) red[t >> 5] = s2;
    __syncthreads();
    if (t < 32) {
        float r = (t < 8) ? red[t] : 0.f;
        #pragma unroll
        for (int o = 4; o > 0; o >>= 1) r += __shfl_xor_sync(0xffffffffu, r, o);
        if (t == 0) stat[1] = rsqrtf(r * (1.0f / DIMD) + 1e-5f);
    }
    __syncthreads();
    y[(size_t)row * DIMD + t] = d * stat[1] * g[t] + b[t];
}

// ---------------- Register-tiled SGEMM 128x128x8, 8x8 micro ----------------
// MODE 0: qkv scatter (+bias) -> g_q/g_k/g_v
// MODE 1: proj: out = extra + (acc+bias)*mask      (NT=256)
// MODE 2: ffn1: out = gelu_exact(acc+bias)         (NT=1024)
// MODE 3: ffn2: out = extra + (acc+bias)*mask      (NT=256)
template<int KD, int NT, int MODE>
__global__ void __launch_bounds__(256)
sgemm_kernel(const float* __restrict__ A,
             const float* __restrict__ W,
             const float* __restrict__ bias,
             const float* __restrict__ extra,
             const int*   __restrict__ nm,
             float* __restrict__ out)
{
    __shared__ float As[8 * 128];
    __shared__ float Bs[8 * 128];

    int t  = threadIdx.x;
    int rm = blockIdx.y * 128;
    int cn = blockIdx.x * 128;
    int ty = t >> 4, tx = t & 15;
    int arow = t >> 1,  aks = (t & 1) << 2;
    int wrow = t >> 5,  wc  = (t & 31) << 2;

    float acc[8][8];
    #pragma unroll
    for (int i = 0; i < 8; ++i)
        #pragma unroll
        for (int j = 0; j < 8; ++j) acc[i][j] = 0.f;

    for (int k0 = 0; k0 < KD; k0 += 8) {
        float4 a4 = *(const float4*)(A + (size_t)(rm + arow) * KD + k0 + aks);
        As[(aks + 0) * 128 + arow] = a4.x;
        As[(aks + 1) * 128 + arow] = a4.y;
        As[(aks + 2) * 128 + arow] = a4.z;
        As[(aks + 3) * 128 + arow] = a4.w;
        float4 w4 = *(const float4*)(W + (size_t)(k0 + wrow) * NT + cn + wc);
        *(float4*)&Bs[wrow * 128 + wc] = w4;
        __syncthreads();
        #pragma unroll
        for (int kk = 0; kk < 8; ++kk) {
            float4 av0 = *(const float4*)&As[kk * 128 + ty * 8];
            float4 av1 = *(const float4*)&As[kk * 128 + ty * 8 + 4];
            float4 bv0 = *(const float4*)&Bs[kk * 128 + tx * 8];
            float4 bv1 = *(const float4*)&Bs[kk * 128 + tx * 8 + 4];
            float aa[8] = {av0.x, av0.y, av0.z, av0.w, av1.x, av1.y, av1.z, av1.w};
            float bb[8] = {bv0.x, bv0.y, bv0.z, bv0.w, bv1.x, bv1.y, bv1.z, bv1.w};
            #pragma unroll
            for (int i = 0; i < 8; ++i)
                #pragma unroll
                for (int j = 0; j < 8; ++j) acc[i][j] += aa[i] * bb[j];
        }
        __syncthreads();
    }

    #pragma unroll
    for (int i = 0; i < 8; ++i) {
        int r = rm + ty * 8 + i;
        float mrow = 0.f;
        if (MODE == 1 || MODE == 3) mrow = nm[r] ? 1.f : 0.f;
        #pragma unroll
        for (int j = 0; j < 8; ++j) {
            int c = cn + tx * 8 + j;
            float val = acc[i][j] + bias[c];
            if (MODE == 0) {
                int part = c >> 8, hh = (c >> 5) & 7, dd = c & 31;
                int bb2 = r >> 11, n = r & 2047;
                float* dst = (part == 0) ? g_q : ((part == 1) ? g_k : g_v);
                dst[((size_t)(bb2 * NHEAD + hh) * NSEQ + n) * HD + dd] = val;
            } else if (MODE == 2) {
                out[(size_t)r * NT + c] = 0.5f * val * (1.f + erff(val * 0.70710678118654752f));
            } else {
                out[(size_t)r * NT + c] = extra[(size_t)r * NT + c] + val * mrow;
            }
        }
    }
}

// ---------------- Flash attention with edge bias + masks ----------------
// block: (b, h, 128 query rows); 256 threads; 16 key tiles of 128
__global__ void __launch_bounds__(256, 1)
attn_kernel(const int*   __restrict__ edge_types,
            const int*   __restrict__ node_mask,
            const float* __restrict__ ebt)
{
    extern __shared__ float sm[];
    float* Qs   = sm;                 // [32][128] (d-major)
    float* Ks   = Qs + 4096;          // [32][128]
    float* Vs   = Ks + 4096;          // [128][32]
    float* S    = Vs + 4096;          // [128][129]
    float* mrow = S + 128 * 129;      // 128
    float* lrow = mrow + 128;         // 128
    float* arow = lrow + 128;         // 128
    float* nmi  = arow + 128;         // 128
    float* nmj  = nmi + 128;          // 128
    float* tbl  = nmj + 128;          // 16

    int tid = threadIdx.x;
    int bid = blockIdx.x;
    int rb = bid & 15, h = (bid >> 4) & 7, b = bid >> 7;
    int r0 = rb * 128;
    const float scale = 0.17677669529663687f;  // 32^-0.5

    const float* qptr = g_q + ((size_t)(b * NHEAD + h) * NSEQ + r0) * HD;
    const float* kbh  = g_k + (size_t)(b * NHEAD + h) * NSEQ * HD;
    const float* vbh  = g_v + (size_t)(b * NHEAD + h) * NSEQ * HD;

    for (int u = tid; u < 1024; u += 256) {
        int row = u >> 3, ds = (u & 7) << 2;
        float4 t4 = *(const float4*)(qptr + row * HD + ds);
        Qs[(ds + 0) * 128 + row] = t4.x;
        Qs[(ds + 1) * 128 + row] = t4.y;
        Qs[(ds + 2) * 128 + row] = t4.z;
        Qs[(ds + 3) * 128 + row] = t4.w;
    }
    if (tid < 128) {
        mrow[tid] = -INFINITY;
        lrow[tid] = 0.f;
        nmi[tid]  = node_mask[b * NSEQ + r0 + tid] ? 1.f : 0.f;
    }
    if (tid < 9) tbl[tid] = ebt[tid * NHEAD + h];

    float acc[4][4];
    #pragma unroll
    for (int i = 0; i < 4; ++i)
        #pragma unroll
        for (int j = 0; j < 4; ++j) acc[i][j] = 0.f;

    int ty = tid >> 4, tx = tid & 15;    // phase-1 16x16 thread grid (8x8 micro)
    int it = tid >> 3, dt = tid & 7;     // phase-3 32x8 thread grid (4x4 micro)
    __syncthreads();

    for (int kt = 0; kt < 16; ++kt) {
        int j0 = kt * 128;
        for (int u = tid; u < 1024; u += 256) {
            int row = u >> 3, ds = (u & 7) << 2;
            float4 t4 = *(const float4*)(kbh + (size_t)(j0 + row) * HD + ds);
            Ks[(ds + 0) * 128 + row] = t4.x;
            Ks[(ds + 1) * 128 + row] = t4.y;
            Ks[(ds + 2) * 128 + row] = t4.z;
            Ks[(ds + 3) * 128 + row] = t4.w;
            float4 v4 = *(const float4*)(vbh + (size_t)(j0 + row) * HD + ds);
            *(float4*)&Vs[row * HD + ds] = v4;
        }
        if (tid < 128) nmj[tid] = node_mask[b * NSEQ + j0 + tid] ? 1.f : 0.f;
        __syncthreads();

        // ---- phase 1: S = Q K^T (8x8 per thread) ----
        float sacc[8][8];
        #pragma unroll
        for (int i = 0; i < 8; ++i)
            #pragma unroll
            for (int j = 0; j < 8; ++j) sacc[i][j] = 0.f;
        int i0 = ty * 8, jj0 = tx * 8;
        #pragma unroll 4
        for (int d = 0; d < 32; ++d) {
            float4 a0 = *(const float4*)&Qs[d * 128 + i0];
            float4 a1 = *(const float4*)&Qs[d * 128 + i0 + 4];
            float4 b0 = *(const float4*)&Ks[d * 128 + jj0];
            float4 b1 = *(const float4*)&Ks[d * 128 + jj0 + 4];
            float aa[8] = {a0.x, a0.y, a0.z, a0.w, a1.x, a1.y, a1.z, a1.w};
            float bb[8] = {b0.x, b0.y, b0.z, b0.w, b1.x, b1.y, b1.z, b1.w};
            #pragma unroll
            for (int i = 0; i < 8; ++i)
                #pragma unroll
                for (int j = 0; j < 8; ++j) sacc[i][j] += aa[i] * bb[j];
        }
        // bias + mask epilogue -> S
        #pragma unroll
        for (int ii = 0; ii < 8; ++ii) {
            int gi = r0 + i0 + ii;
            float nm_i = nmi[i0 + ii];
            const int* et = edge_types + ((size_t)b * NSEQ + gi) * NSEQ + j0 + jj0;
            int4 e0 = *(const int4*)et;
            int4 e1 = *(const int4*)(et + 4);
            int ev[8] = {e0.x, e0.y, e0.z, e0.w, e1.x, e1.y, e1.z, e1.w};
            #pragma unroll
            for (int jj = 0; jj < 8; ++jj) {
                int gj = j0 + jj0 + jj;
                bool ok = ((ev[jj] != 0) || (gi == gj)) && (nm_i != 0.f) && (nmj[jj0 + jj] != 0.f);
                S[(i0 + ii) * 129 + jj0 + jj] =
                    ok ? sacc[ii][jj] * scale + tbl[ev[jj]] : -1e9f;
            }
        }
        __syncthreads();

        // ---- phase 2: online softmax, one thread per row ----
        if (tid < 128) {
            float* srow = S + tid * 129;
            float m_old = mrow[tid];
            float mt = m_old;
            #pragma unroll 4
            for (int j = 0; j < 128; ++j) mt = fmaxf(mt, srow[j]);
            float ls = 0.f;
            #pragma unroll 4
            for (int j = 0; j < 128; ++j) {
                float p = __expf(srow[j] - mt);
                srow[j] = p;
                ls += p;
            }
            float al = __expf(m_old - mt);
            arow[tid] = al;
            mrow[tid] = mt;
            lrow[tid] = lrow[tid] * al + ls;
        }
        __syncthreads();

        // ---- phase 3: rescale + O += P V (4x4 per thread) ----
        int pi0 = it * 4, pd0 = dt * 4;
        float al0 = arow[pi0], al1 = arow[pi0 + 1], al2 = arow[pi0 + 2], al3 = arow[pi0 + 3];
        #pragma unroll
        for (int dd = 0; dd < 4; ++dd) {
            acc[0][dd] *= al0; acc[1][dd] *= al1; acc[2][dd] *= al2; acc[3][dd] *= al3;
        }
        #pragma unroll 4
        for (int j = 0; j < 128; ++j) {
            float p0 = S[(pi0 + 0) * 129 + j];
            float p1 = S[(pi0 + 1) * 129 + j];
            float p2 = S[(pi0 + 2) * 129 + j];
            float p3 = S[(pi0 + 3) * 129 + j];
            float4 vv = *(const float4*)&Vs[j * HD + pd0];
            acc[0][0] += p0 * vv.x; acc[0][1] += p0 * vv.y; acc[0][2] += p0 * vv.z; acc[0][3] += p0 * vv.w;
            acc[1][0] += p1 * vv.x; acc[1][1] += p1 * vv.y; acc[1][2] += p1 * vv.z; acc[1][3] += p1 * vv.w;
            acc[2][0] += p2 * vv.x; acc[2][1] += p2 * vv.y; acc[2][2] += p2 * vv.z; acc[2][3] += p2 * vv.w;
            acc[3][0] += p3 * vv.x; acc[3][1] += p3 * vv.y; acc[3][2] += p3 * vv.z; acc[3][3] += p3 * vv.w;
        }
        __syncthreads();
    }

    // write out: [B,N,DIM] with DIM index = h*32+d
    int pi0 = it * 4, pd0 = dt * 4;
    #pragma unroll
    for (int ii = 0; ii < 4; ++ii) {
        float inv = 1.f / lrow[pi0 + ii];
        int n = r0 + pi0 + ii;
        float4 o;
        o.x = acc[ii][0] * inv; o.y = acc[ii][1] * inv;
        o.z = acc[ii][2] * inv; o.w = acc[ii][3] * inv;
        *(float4*)(g_ao + ((size_t)b * NSEQ + n) * DIMD + h * HD + pd0) = o;
    }
}

// ---------------- launch ----------------
static void* sym_addr(const void* sym)
{
    void* p = nullptr;
    cudaGetSymbolAddress(&p, sym);
    return p;
}

extern "C" void kernel_launch(void* const* d_in, const int* in_sizes, int n_in,
                              void* d_out, int out_size)
{
    const float* x      = (const float*)d_in[0];
    const int*   etyp   = (const int*)  d_in[1];
    const int*   nmask  = (const int*)  d_in[2];
    const float* qkv_w  = (const float*)d_in[3];
    const float* qkv_b  = (const float*)d_in[4];
    const float* proj_w = (const float*)d_in[5];
    const float* proj_b = (const float*)d_in[6];
    const float* ebt    = (const float*)d_in[7];
    const float* ln1_g  = (const float*)d_in[8];
    const float* ln1_b  = (const float*)d_in[9];
    const float* ln2_g  = (const float*)d_in[10];
    const float* ln2_b  = (const float*)d_in[11];
    const float* ffn_w1 = (const float*)d_in[12];
    const float* ffn_b1 = (const float*)d_in[13];
    const float* ffn_w2 = (const float*)d_in[14];
    const float* ffn_b2 = (const float*)d_in[15];
    float* out = (float*)d_out;

    float* ph   = (float*)sym_addr(g_h);
    float* pao  = (float*)sym_addr(g_ao);
    float* px1  = (float*)sym_addr(g_x1);
    float* ph2  = (float*)sym_addr(g_h2);
    float* pmid = (float*)sym_addr(g_mid);

    const int ATTN_SMEM = (3 * 4096 + 128 * 129 + 5 * 128 + 16) * (int)sizeof(float);
    cudaFuncSetAttribute(attn_kernel, cudaFuncAttributeMaxDynamicSharedMemorySize, ATTN_SMEM);

    // 1) LN1
    ln_kernel<<<ROWS, 256>>>(x, ln1_g, ln1_b, ph);
    // 2) QKV GEMM + scatter
    sgemm_kernel<DIMD, 3 * DIMD, 0><<<dim3(6, 32), 256>>>(ph, qkv_w, qkv_b, nullptr, nullptr, nullptr);
    // 3) attention (flash-style, edge bias + masks)
    attn_kernel<<<BNUM * NHEAD * (NSEQ / 128), 256, ATTN_SMEM>>>(etyp, nmask, ebt);
    // 4) proj + residual + node mask -> x1
    sgemm_kernel<DIMD, DIMD, 1><<<dim3(2, 32), 256>>>(pao, proj_w, proj_b, x, nmask, px1);
    // 5) LN2
    ln_kernel<<<ROWS, 256>>>(px1, ln2_g, ln2_b, ph2);
    // 6) FFN1 + exact GELU
    sgemm_kernel<DIMD, FFD, 2><<<dim3(8, 32), 256>>>(ph2, ffn_w1, ffn_b1, nullptr, nullptr, pmid);
    // 7) FFN2 + node mask + residual -> out
    sgemm_kernel<FFD, DIMD, 3><<<dim3(2, 32), 256>>>(pmid, ffn_w2, ffn_b2, px1, nmask, out);
}

// round 2
// speedup vs baseline: 2.1782x; 2.1782x over previous
#include <cuda_runtime.h>
#include <math.h>
#include <stdint.h>

#define BNUM 2
#define NSEQ 2048
#define DIMD 256
#define NHEAD 8
#define HD 32
#define FFD 1024
#define ROWS (BNUM*NSEQ)   // 4096

// ---------------- scratch (device globals, no allocation) ----------------
__device__ float g_h [ROWS*DIMD];
__device__ float g_q [BNUM*NHEAD*NSEQ*HD];
__device__ float g_k [BNUM*NHEAD*NSEQ*HD];
__device__ float g_v [BNUM*NHEAD*NSEQ*HD];
__device__ float g_ao[ROWS*DIMD];
__device__ float g_x1[ROWS*DIMD];
__device__ float g_h2[ROWS*DIMD];
__device__ float g_mid[ROWS*FFD];

// ---------------- helpers ----------------
__device__ __forceinline__ float to_tf32(float x){
    uint32_t u; asm("cvt.rna.tf32.f32 %0, %1;" : "=r"(u) : "f"(x));
    return __uint_as_float(u);
}
__device__ __forceinline__ void mma8(float* c,
    uint32_t a0, uint32_t a1, uint32_t a2, uint32_t a3,
    uint32_t b0, uint32_t b1)
{
    asm volatile("mma.sync.aligned.m16n8k8.row.col.f32.tf32.tf32.f32 "
        "{%0,%1,%2,%3}, {%4,%5,%6,%7}, {%8,%9}, {%0,%1,%2,%3};"
        : "+f"(c[0]), "+f"(c[1]), "+f"(c[2]), "+f"(c[3])
        : "r"(a0), "r"(a1), "r"(a2), "r"(a3), "r"(b0), "r"(b1));
}

// ---------------- LayerNorm: one block per row of 256 ----------------
__global__ void ln_kernel(const float* __restrict__ x,
                          const float* __restrict__ g,
                          const float* __restrict__ b,
                          float* __restrict__ y)
{
    int row = blockIdx.x;
    int t   = threadIdx.x;
    const float* xr = x + (size_t)row * DIMD;
    float v = xr[t];

    __shared__ float red[8];
    __shared__ float stat[2];

    float s = v;
    #pragma unroll
    for (int o = 16; o > 0; o >>= 1) s += __shfl_xor_sync(0xffffffffu, s, o);
    if ((t & 31) == 0) red[t >> 5] = s;
    __syncthreads();
    if (t < 32) {
        float r = (t < 8) ? red[t] : 0.f;
        #pragma unroll
        for (int o = 4; o > 0; o >>= 1) r += __shfl_xor_sync(0xffffffffu, r, o);
        if (t == 0) stat[0] = r * (1.0f / DIMD);
    }
    __syncthreads();
    float mu = stat[0];
    float d  = v - mu;

    float s2 = d * d;
    #pragma unroll
    for (int o = 16; o > 0; o >>= 1) s2 += __shfl_xor_sync(0xffffffffu, s2, o);
    if ((t & 31) == 0) red[t >> 5] = s2;
    __syncthreads();
    if (t < 32) {
        float r = (t < 8) ? red[t] : 0.f;
        #pragma unroll
        for (int o = 4; o > 0; o >>= 1) r += __shfl_xor_sync(0xffffffffu, r, o);
        if (t == 0) stat[1] = rsqrtf(r * (1.0f / DIMD) + 1e-5f);
    }
    __syncthreads();
    y[(size_t)row * DIMD + t] = d * stat[1] * g[t] + b[t];
}

// ---------------- TF32 MMA GEMM: BM=128, BN=64, BK=32, 8 warps ----------------
// warp grid 4(m) x 2(n), warp tile 32x32 (2 m-tiles x 4 n-tiles of m16n8)
// MODE 0: qkv scatter (+bias)
// MODE 1: proj: out = extra + (acc+bias)*mask
// MODE 2: ffn1: out = gelu_exact(acc+bias)
// MODE 3: ffn2: out = extra + (acc+bias)*mask
template<int KD, int NT, int MODE>
__global__ void __launch_bounds__(256)
mma_gemm(const float* __restrict__ A, const float* __restrict__ W,
         const float* __restrict__ bias, const float* __restrict__ extra,
         const int* __restrict__ nm, float* __restrict__ out)
{
    __shared__ float As[128 * 36];  // [m][k] stride 36 -> frag banks 4*gid+tig
    __shared__ float Bs[32 * 72];   // [k][n] stride 72 -> frag banks 8*tig+gid

    int t = threadIdx.x, lane = t & 31, warp = t >> 5;
    int gid = lane >> 2, tig = lane & 3;
    int wm = warp & 3, wn = warp >> 2;
    int rm = blockIdx.y * 128, cn = blockIdx.x * 64;

    float acc[2][4][4];
    #pragma unroll
    for (int mi = 0; mi < 2; ++mi)
        #pragma unroll
        for (int nt = 0; nt < 4; ++nt)
            #pragma unroll
            for (int q = 0; q < 4; ++q) acc[mi][nt][q] = 0.f;

    int arow = t >> 1, akc = (t & 1) * 16;
    int brow = t >> 3, bnc = (t & 7) * 8;

    for (int k0 = 0; k0 < KD; k0 += 32) {
        const float* ag = A + (size_t)(rm + arow) * KD + k0 + akc;
        #pragma unroll
        for (int i = 0; i < 4; ++i) {
            float4 v = *(const float4*)(ag + 4 * i);
            float* d = &As[arow * 36 + akc + 4 * i];
            d[0] = to_tf32(v.x); d[1] = to_tf32(v.y);
            d[2] = to_tf32(v.z); d[3] = to_tf32(v.w);
        }
        const float* bg = W + (size_t)(k0 + brow) * NT + cn + bnc;
        #pragma unroll
        for (int i = 0; i < 2; ++i) {
            float4 v = *(const float4*)(bg + 4 * i);
            float* d = &Bs[brow * 72 + bnc + 4 * i];
            d[0] = to_tf32(v.x); d[1] = to_tf32(v.y);
            d[2] = to_tf32(v.z); d[3] = to_tf32(v.w);
        }
        __syncthreads();

        const uint32_t* Asu = (const uint32_t*)As;
        const uint32_t* Bsu = (const uint32_t*)Bs;
        #pragma unroll
        for (int ks = 0; ks < 4; ++ks) {
            uint32_t af[2][4];
            #pragma unroll
            for (int mi = 0; mi < 2; ++mi) {
                int rb2 = wm * 32 + mi * 16;
                af[mi][0] = Asu[(rb2 + gid    ) * 36 + ks * 8 + tig    ];
                af[mi][1] = Asu[(rb2 + gid + 8) * 36 + ks * 8 + tig    ];
                af[mi][2] = Asu[(rb2 + gid    ) * 36 + ks * 8 + tig + 4];
                af[mi][3] = Asu[(rb2 + gid + 8) * 36 + ks * 8 + tig + 4];
            }
            #pragma unroll
            for (int nt = 0; nt < 4; ++nt) {
                uint32_t b0 = Bsu[(ks * 8 + tig    ) * 72 + wn * 32 + nt * 8 + gid];
                uint32_t b1 = Bsu[(ks * 8 + tig + 4) * 72 + wn * 32 + nt * 8 + gid];
                mma8(acc[0][nt], af[0][0], af[0][1], af[0][2], af[0][3], b0, b1);
                mma8(acc[1][nt], af[1][0], af[1][1], af[1][2], af[1][3], b0, b1);
            }
        }
        __syncthreads();
    }

    // epilogue (C layout: c0:(gid, 2*tig) c1:(gid, 2*tig+1) c2:(gid+8,..) c3)
    #pragma unroll
    for (int mi = 0; mi < 2; ++mi) {
        #pragma unroll
        for (int half = 0; half < 2; ++half) {
            int r = rm + wm * 32 + mi * 16 + gid + half * 8;
            float mrow = 0.f;
            if (MODE == 1 || MODE == 3) mrow = nm[r] ? 1.f : 0.f;
            #pragma unroll
            for (int nt = 0; nt < 4; ++nt) {
                int c = cn + wn * 32 + nt * 8 + tig * 2;
                float v0 = acc[mi][nt][half * 2 + 0] + bias[c];
                float v1 = acc[mi][nt][half * 2 + 1] + bias[c + 1];
                if (MODE == 0) {
                    int part = c >> 8, hh = (c >> 5) & 7, dd = c & 31;
                    int b2 = r >> 11, n = r & 2047;
                    float* dst = (part == 0) ? g_q : ((part == 1) ? g_k : g_v);
                    *(float2*)&dst[((size_t)(b2 * NHEAD + hh) * NSEQ + n) * HD + dd] =
                        make_float2(v0, v1);
                } else if (MODE == 2) {
                    float g0 = 0.5f * v0 * (1.f + erff(v0 * 0.70710678118654752f));
                    float g1 = 0.5f * v1 * (1.f + erff(v1 * 0.70710678118654752f));
                    *(float2*)&out[(size_t)r * NT + c] = make_float2(g0, g1);
                } else {
                    float2 ex = *(const float2*)&extra[(size_t)r * NT + c];
                    *(float2*)&out[(size_t)r * NT + c] =
                        make_float2(ex.x + v0 * mrow, ex.y + v1 * mrow);
                }
            }
        }
    }
}

// ---------------- TF32 MMA flash attention, fixed-max softmax ----------------
// block: 128 q rows, 8 warps, 16 key tiles of 128
// QK: warps 4(m) x 2(n): warp 32 rows x 64 cols.  PV: warp w -> rows w*16..+15
__global__ void __launch_bounds__(256)
attn_mma(const int*   __restrict__ edge_types,
         const int*   __restrict__ node_mask,
         const float* __restrict__ ebt)
{
    extern __shared__ float sm[];
    float* Qs   = sm;                  // [128][36]
    float* Ks   = Qs + 128 * 36;       // [128][36]
    float* Vs   = Ks + 128 * 36;       // [128][40]
    float* S    = Vs + 128 * 40;       // [128][132]  (P, tf32)
    float* lsum = S + 128 * 132;       // 128
    float* nmi  = lsum + 128;          // 128
    float* nmj  = nmi + 128;           // 128
    float* tbl  = nmj + 128;           // 16

    int tid = threadIdx.x, lane = tid & 31, warp = tid >> 5;
    int gid = lane >> 2, tig = lane & 3;
    int wm = warp & 3, wn = warp >> 2;
    int bid = blockIdx.x;
    int h = bid & 7, rb = (bid >> 3) & 15, b = bid >> 7;  // h fastest: L2 reuse of edges
    int r0 = rb * 128;
    const float scale = 0.17677669529663687f;

    const float* qptr = g_q + ((size_t)(b * NHEAD + h) * NSEQ + r0) * HD;
    const float* kbh  = g_k + (size_t)(b * NHEAD + h) * NSEQ * HD;
    const float* vbh  = g_v + (size_t)(b * NHEAD + h) * NSEQ * HD;

    int lrow = tid >> 1, ldc = (tid & 1) * 16;
    {
        const float* qg = qptr + (size_t)lrow * HD + ldc;
        #pragma unroll
        for (int i = 0; i < 4; ++i) {
            float4 v = *(const float4*)(qg + 4 * i);
            float* d = &Qs[lrow * 36 + ldc + 4 * i];
            d[0] = to_tf32(v.x); d[1] = to_tf32(v.y);
            d[2] = to_tf32(v.z); d[3] = to_tf32(v.w);
        }
    }
    if (tid < 128) {
        lsum[tid] = 0.f;
        nmi[tid]  = node_mask[b * NSEQ + r0 + tid] ? 1.f : 0.f;
    }
    if (tid < 9) tbl[tid] = ebt[tid * NHEAD + h];
    __syncthreads();

    // preload Q fragments (fixed across all key tiles)
    const uint32_t* Qsu = (const uint32_t*)Qs;
    uint32_t qa[2][4][4];
    #pragma unroll
    for (int mi = 0; mi < 2; ++mi) {
        int rb2 = wm * 32 + mi * 16;
        #pragma unroll
        for (int ks = 0; ks < 4; ++ks) {
            qa[mi][ks][0] = Qsu[(rb2 + gid    ) * 36 + ks * 8 + tig    ];
            qa[mi][ks][1] = Qsu[(rb2 + gid + 8) * 36 + ks * 8 + tig    ];
            qa[mi][ks][2] = Qsu[(rb2 + gid    ) * 36 + ks * 8 + tig + 4];
            qa[mi][ks][3] = Qsu[(rb2 + gid + 8) * 36 + ks * 8 + tig + 4];
        }
    }
    float nmi_r[2][2];
    #pragma unroll
    for (int mi = 0; mi < 2; ++mi) {
        nmi_r[mi][0] = nmi[wm * 32 + mi * 16 + gid];
        nmi_r[mi][1] = nmi[wm * 32 + mi * 16 + gid + 8];
    }

    float oacc[4][4];
    #pragma unroll
    for (int nt = 0; nt < 4; ++nt)
        #pragma unroll
        for (int q = 0; q < 4; ++q) oacc[nt][q] = 0.f;
    int w16 = warp * 16;

    for (int kt = 0; kt < 16; ++kt) {
        int j0 = kt * 128;
        {
            const float* kg = kbh + (size_t)(j0 + lrow) * HD + ldc;
            const float* vg = vbh + (size_t)(j0 + lrow) * HD + ldc;
            #pragma unroll
            for (int i = 0; i < 4; ++i) {
                float4 v = *(const float4*)(kg + 4 * i);
                float* d = &Ks[lrow * 36 + ldc + 4 * i];
                d[0] = to_tf32(v.x); d[1] = to_tf32(v.y);
                d[2] = to_tf32(v.z); d[3] = to_tf32(v.w);
                float4 w = *(const float4*)(vg + 4 * i);
                float* e = &Vs[lrow * 40 + ldc + 4 * i];
                e[0] = to_tf32(w.x); e[1] = to_tf32(w.y);
                e[2] = to_tf32(w.z); e[3] = to_tf32(w.w);
            }
        }
        if (tid < 128) nmj[tid] = node_mask[b * NSEQ + j0 + tid] ? 1.f : 0.f;
        __syncthreads();

        // ---- QK^T MMA ----
        const uint32_t* Ksu = (const uint32_t*)Ks;
        float sacc[2][8][4];
        #pragma unroll
        for (int mi = 0; mi < 2; ++mi)
            #pragma unroll
            for (int nt = 0; nt < 8; ++nt)
                #pragma unroll
                for (int q = 0; q < 4; ++q) sacc[mi][nt][q] = 0.f;
        #pragma unroll
        for (int ks = 0; ks < 4; ++ks) {
            #pragma unroll
            for (int nt = 0; nt < 8; ++nt) {
                int kb = wn * 64 + nt * 8;
                uint32_t b0 = Ksu[(kb + gid) * 36 + ks * 8 + tig    ];
                uint32_t b1 = Ksu[(kb + gid) * 36 + ks * 8 + tig + 4];
                mma8(sacc[0][nt], qa[0][ks][0], qa[0][ks][1], qa[0][ks][2], qa[0][ks][3], b0, b1);
                mma8(sacc[1][nt], qa[1][ks][0], qa[1][ks][1], qa[1][ks][2], qa[1][ks][3], b0, b1);
            }
        }

        // ---- epilogue: bias + mask + exp (fixed max 0), write P, row sums ----
        float lp[2][2] = {{0.f, 0.f}, {0.f, 0.f}};
        #pragma unroll
        for (int mi = 0; mi < 2; ++mi) {
            #pragma unroll
            for (int nt = 0; nt < 8; ++nt) {
                int ccol = wn * 64 + nt * 8 + tig * 2;
                int gj = j0 + ccol;
                float nj0 = nmj[ccol], nj1 = nmj[ccol + 1];
                #pragma unroll
                for (int half = 0; half < 2; ++half) {
                    int rloc = wm * 32 + mi * 16 + gid + half * 8;
                    int gi = r0 + rloc;
                    int2 ee = *(const int2*)(edge_types +
                              ((size_t)b * NSEQ + gi) * NSEQ + gj);
                    float ni = nmi_r[mi][half];
                    bool ok0 = ((ee.x != 0) | (gi == gj    )) && (ni != 0.f) && (nj0 != 0.f);
                    bool ok1 = ((ee.y != 0) | (gi == gj + 1)) && (ni != 0.f) && (nj1 != 0.f);
                    float p0 = ok0 ? __expf(sacc[mi][nt][half * 2 + 0] * scale + tbl[ee.x]) : 0.f;
                    float p1 = ok1 ? __expf(sacc[mi][nt][half * 2 + 1] * scale + tbl[ee.y]) : 0.f;
                    lp[mi][half] += p0 + p1;
                    *(float2*)&S[rloc * 132 + ccol] = make_float2(to_tf32(p0), to_tf32(p1));
                }
            }
        }
        #pragma unroll
        for (int mi = 0; mi < 2; ++mi) {
            #pragma unroll
            for (int half = 0; half < 2; ++half) {
                float v = lp[mi][half];
                v += __shfl_xor_sync(0xffffffffu, v, 1);
                v += __shfl_xor_sync(0xffffffffu, v, 2);
                if (tig == 0)
                    atomicAdd(&lsum[wm * 32 + mi * 16 + gid + half * 8], v);
            }
        }
        __syncthreads();

        // ---- PV MMA: O += P[128x128] * V[128x32] ----
        const uint32_t* Su  = (const uint32_t*)S;
        const uint32_t* Vsu = (const uint32_t*)Vs;
        #pragma unroll
        for (int ks = 0; ks < 16; ++ks) {
            uint32_t a0 = Su[(w16 + gid    ) * 132 + ks * 8 + tig    ];
            uint32_t a1 = Su[(w16 + gid + 8) * 132 + ks * 8 + tig    ];
            uint32_t a2 = Su[(w16 + gid    ) * 132 + ks * 8 + tig + 4];
            uint32_t a3 = Su[(w16 + gid + 8) * 132 + ks * 8 + tig + 4];
            #pragma unroll
            for (int nt = 0; nt < 4; ++nt) {
                uint32_t b0 = Vsu[(ks * 8 + tig    ) * 40 + nt * 8 + gid];
                uint32_t b1 = Vsu[(ks * 8 + tig + 4) * 40 + nt * 8 + gid];
                mma8(oacc[nt], a0, a1, a2, a3, b0, b1);
            }
        }
        __syncthreads();
    }

    // ---- normalize + write [B,N,DIM] ----
    float lv0 = lsum[w16 + gid], lv1 = lsum[w16 + gid + 8];
    float inv0 = lv0 > 0.f ? 1.f / lv0 : 0.f;
    float inv1 = lv1 > 0.f ? 1.f / lv1 : 0.f;
    float* od = g_ao + ((size_t)b * NSEQ + r0) * DIMD + h * HD;
    #pragma unroll
    for (int nt = 0; nt < 4; ++nt) {
        int d = nt * 8 + tig * 2;
        *(float2*)&od[(size_t)(w16 + gid    ) * DIMD + d] =
            make_float2(oacc[nt][0] * inv0, oacc[nt][1] * inv0);
        *(float2*)&od[(size_t)(w16 + gid + 8) * DIMD + d] =
            make_float2(oacc[nt][2] * inv1, oacc[nt][3] * inv1);
    }
}

// ---------------- launch ----------------
static void* sym_addr(const void* sym)
{
    void* p = nullptr;
    cudaGetSymbolAddress(&p, sym);
    return p;
}

extern "C" void kernel_launch(void* const* d_in, const int* in_sizes, int n_in,
                              void* d_out, int out_size)
{
    const float* x      = (const float*)d_in[0];
    const int*   etyp   = (const int*)  d_in[1];
    const int*   nmask  = (const int*)  d_in[2];
    const float* qkv_w  = (const float*)d_in[3];
    const float* qkv_b  = (const float*)d_in[4];
    const float* proj_w = (const float*)d_in[5];
    const float* proj_b = (const float*)d_in[6];
    const float* ebt    = (const float*)d_in[7];
    const float* ln1_g  = (const float*)d_in[8];
    const float* ln1_b  = (const float*)d_in[9];
    const float* ln2_g  = (const float*)d_in[10];
    const float* ln2_b  = (const float*)d_in[11];
    const float* ffn_w1 = (const float*)d_in[12];
    const float* ffn_b1 = (const float*)d_in[13];
    const float* ffn_w2 = (const float*)d_in[14];
    const float* ffn_b2 = (const float*)d_in[15];
    float* out = (float*)d_out;

    float* ph   = (float*)sym_addr(g_h);
    float* pao  = (float*)sym_addr(g_ao);
    float* px1  = (float*)sym_addr(g_x1);
    float* ph2  = (float*)sym_addr(g_h2);
    float* pmid = (float*)sym_addr(g_mid);

    const int ATTN_SMEM = (128*36*2 + 128*40 + 128*132 + 3*128 + 16) * (int)sizeof(float);
    cudaFuncSetAttribute(attn_mma, cudaFuncAttributeMaxDynamicSharedMemorySize, ATTN_SMEM);

    // 1) LN1
    ln_kernel<<<ROWS, 256>>>(x, ln1_g, ln1_b, ph);
    // 2) QKV GEMM + scatter
    mma_gemm<DIMD, 3 * DIMD, 0><<<dim3(12, 32), 256>>>(ph, qkv_w, qkv_b, nullptr, nullptr, nullptr);
    // 3) attention (tf32 mma, fixed-max softmax)
    attn_mma<<<BNUM * NHEAD * (NSEQ / 128), 256, ATTN_SMEM>>>(etyp, nmask, ebt);
    // 4) proj + residual + node mask -> x1
    mma_gemm<DIMD, DIMD, 1><<<dim3(4, 32), 256>>>(pao, proj_w, proj_b, x, nmask, px1);
    // 5) LN2
    ln_kernel<<<ROWS, 256>>>(px1, ln2_g, ln2_b, ph2);
    // 6) FFN1 + exact GELU
    mma_gemm<DIMD, FFD, 2><<<dim3(16, 32), 256>>>(ph2, ffn_w1, ffn_b1, nullptr, nullptr, pmid);
    // 7) FFN2 + node mask + residual -> out
    mma_gemm<FFD, DIMD, 3><<<dim3(4, 32), 256>>>(pmid, ffn_w2, ffn_b2, px1, nmask, out);
}

// round 3
// speedup vs baseline: 3.8774x; 1.7801x over previous
#include <cuda_runtime.h>
#include <cuda_bf16.h>
#include <math.h>
#include <stdint.h>

#define BNUM 2
#define NSEQ 2048
#define DIMD 256
#define NHEAD 8
#define HD 32
#define FFD 1024
#define ROWS (BNUM*NSEQ)   // 4096

typedef __nv_bfloat16 bf16;

// ---------------- scratch (device globals, no allocation) ----------------
__device__ bf16  g_h  [ROWS*DIMD];
__device__ bf16  g_q  [BNUM*NHEAD*NSEQ*HD];
__device__ bf16  g_k  [BNUM*NHEAD*NSEQ*HD];
__device__ bf16  g_vT [BNUM*NHEAD*HD*NSEQ];   // [b][h][d][n]
__device__ bf16  g_ao [ROWS*DIMD];
__device__ float g_x1 [ROWS*DIMD];
__device__ bf16  g_h2 [ROWS*DIMD];
__device__ bf16  g_mid[ROWS*FFD];
__device__ bf16  g_wqkv [3*DIMD*DIMD];  // [768][256]  (n-major, k contiguous)
__device__ bf16  g_wproj[DIMD*DIMD];    // [256][256]
__device__ bf16  g_wf1  [FFD*DIMD];     // [1024][256]
__device__ bf16  g_wf2  [DIMD*FFD];     // [256][1024]

// ---------------- helpers ----------------
__device__ __forceinline__ void cpasync16(void* sdst, const void* gsrc){
    unsigned s = (unsigned)__cvta_generic_to_shared(sdst);
    asm volatile("cp.async.cg.shared.global [%0], [%1], 16;" :: "r"(s), "l"(gsrc));
}
#define CP_COMMIT() asm volatile("cp.async.commit_group;")
#define CP_WAIT0()  asm volatile("cp.async.wait_group 0;")

__device__ __forceinline__ void mma16(float* c,
    uint32_t a0, uint32_t a1, uint32_t a2, uint32_t a3,
    uint32_t b0, uint32_t b1)
{
    asm volatile("mma.sync.aligned.m16n8k16.row.col.f32.bf16.bf16.f32 "
        "{%0,%1,%2,%3}, {%4,%5,%6,%7}, {%8,%9}, {%0,%1,%2,%3};"
        : "+f"(c[0]), "+f"(c[1]), "+f"(c[2]), "+f"(c[3])
        : "r"(a0), "r"(a1), "r"(a2), "r"(a3), "r"(b0), "r"(b1));
}

// ---------------- weight convert: W[k][n] fp32 -> Wt[n][k] bf16 ----------------
__global__ void wconv(const float* __restrict__ W, bf16* __restrict__ Wt, int K, int N)
{
    int i = blockIdx.x * 256 + threadIdx.x;
    if (i < K * N) {
        int k = i / N, n = i % N;
        Wt[(size_t)n * K + k] = __float2bfloat16(W[i]);
    }
}

// ---------------- LayerNorm: one block per row of 256, bf16 out ----------------
__global__ void ln_kernel(const float* __restrict__ x,
                          const float* __restrict__ g,
                          const float* __restrict__ b,
                          bf16* __restrict__ y)
{
    int row = blockIdx.x;
    int t   = threadIdx.x;
    float v = x[(size_t)row * DIMD + t];

    __shared__ float red[8];
    __shared__ float stat[2];

    float s = v;
    #pragma unroll
    for (int o = 16; o > 0; o >>= 1) s += __shfl_xor_sync(0xffffffffu, s, o);
    if ((t & 31) == 0) red[t >> 5] = s;
    __syncthreads();
    if (t < 32) {
        float r = (t < 8) ? red[t] : 0.f;
        #pragma unroll
        for (int o = 4; o > 0; o >>= 1) r += __shfl_xor_sync(0xffffffffu, r, o);
        if (t == 0) stat[0] = r * (1.0f / DIMD);
    }
    __syncthreads();
    float mu = stat[0];
    float d  = v - mu;

    float s2 = d * d;
    #pragma unroll
    for (int o = 16; o > 0; o >>= 1) s2 += __shfl_xor_sync(0xffffffffu, s2, o);
    if ((t & 31) == 0) red[t >> 5] = s2;
    __syncthreads();
    if (t < 32) {
        float r = (t < 8) ? red[t] : 0.f;
        #pragma unroll
        for (int o = 4; o > 0; o >>= 1) r += __shfl_xor_sync(0xffffffffu, r, o);
        if (t == 0) stat[1] = rsqrtf(r * (1.0f / DIMD) + 1e-5f);
    }
    __syncthreads();
    y[(size_t)row * DIMD + t] = __float2bfloat16(d * stat[1] * g[t] + b[t]);
}

// ---------------- bf16 MMA GEMM, 2-stage cp.async pipeline ----------------
// A: [M][KD] bf16 row-major.  Wt: [NT][KD] bf16 (k contiguous).
// MODE 0: qkv scatter (+bias) -> g_q/g_k(normal), g_vT(transposed)
// MODE 1: proj: outf = extra + (acc+bias)*mask
// MODE 2: ffn1: outb = bf16(gelu_exact(acc+bias))
// MODE 3: ffn2: outf = extra + (acc+bias)*mask
template<int BM, int BN, int KD, int NT, int MODE>
__global__ void __launch_bounds__(256, 2)
mma_gemm(const bf16* __restrict__ A, const bf16* __restrict__ Wt,
         const float* __restrict__ bias, const float* __restrict__ extra,
         const int* __restrict__ nm, float* __restrict__ outf, bf16* __restrict__ outb)
{
    constexpr int WM  = BM / 32;        // warps along m
    constexpr int WN  = 8 / WM;         // warps along n
    constexpr int WTN = BN / WN;        // warp tile n
    constexpr int NTN = WTN / 8;        // n8 tiles per warp
    constexpr int CA  = (BM * 32 / 8) / 256;  // 16B chunks per thread for A
    constexpr int CB  = (BN * 32 / 8) / 256;

    __shared__ __align__(16) bf16 As[2][BM * 40];
    __shared__ __align__(16) bf16 Bs[2][BN * 40];

    int t = threadIdx.x, lane = t & 31, warp = t >> 5;
    int gid = lane >> 2, tig = lane & 3;
    int wm = warp % WM, wn = warp / WM;
    int rm = blockIdx.y * BM, cn = blockIdx.x * BN;
    const bf16* Ag = A  + (size_t)rm * KD;
    const bf16* Bg = Wt + (size_t)cn * KD;

    float acc[2][NTN][4];
    #pragma unroll
    for (int mi = 0; mi < 2; ++mi)
        #pragma unroll
        for (int nt = 0; nt < NTN; ++nt)
            #pragma unroll
            for (int q = 0; q < 4; ++q) acc[mi][nt][q] = 0.f;

    auto load_stage = [&](int k0, int st) {
        #pragma unroll
        for (int i = 0; i < CA; ++i) {
            int c = t + i * 256, row = c >> 2, off = (c & 3) * 8;
            cpasync16(&As[st][row * 40 + off], Ag + (size_t)row * KD + k0 + off);
        }
        #pragma unroll
        for (int i = 0; i < CB; ++i) {
            int c = t + i * 256, row = c >> 2, off = (c & 3) * 8;
            cpasync16(&Bs[st][row * 40 + off], Bg + (size_t)row * KD + k0 + off);
        }
        CP_COMMIT();
    };

    load_stage(0, 0);
    for (int k0 = 0; k0 < KD; k0 += 32) {
        int st = (k0 >> 5) & 1;
        CP_WAIT0();
        __syncthreads();
        if (k0 + 32 < KD) load_stage(k0 + 32, st ^ 1);

        const uint32_t* A32 = (const uint32_t*)As[st];
        const uint32_t* B32 = (const uint32_t*)Bs[st];
        #pragma unroll
        for (int ks = 0; ks < 2; ++ks) {
            uint32_t af[2][4];
            #pragma unroll
            for (int mi = 0; mi < 2; ++mi) {
                int base = wm * 32 + mi * 16;
                af[mi][0] = A32[(base + gid    ) * 20 + ks * 8 + tig    ];
                af[mi][1] = A32[(base + gid + 8) * 20 + ks * 8 + tig    ];
                af[mi][2] = A32[(base + gid    ) * 20 + ks * 8 + tig + 4];
                af[mi][3] = A32[(base + gid + 8) * 20 + ks * 8 + tig + 4];
            }
            #pragma unroll
            for (int nt = 0; nt < NTN; ++nt) {
                int n = wn * WTN + nt * 8 + gid;
                uint32_t b0 = B32[n * 20 + ks * 8 + tig];
                uint32_t b1 = B32[n * 20 + ks * 8 + tig + 4];
                mma16(acc[0][nt], af[0][0], af[0][1], af[0][2], af[0][3], b0, b1);
                mma16(acc[1][nt], af[1][0], af[1][1], af[1][2], af[1][3], b0, b1);
            }
        }
        // no trailing sync: next iter's wait+sync orders reuse of this buffer
    }
    __syncthreads();

    // ---- epilogue ----
    #pragma unroll
    for (int mi = 0; mi < 2; ++mi) {
        #pragma unroll
        for (int half = 0; half < 2; ++half) {
            int r = rm + wm * 32 + mi * 16 + gid + half * 8;
            float mrow = 0.f;
            if (MODE == 1 || MODE == 3) mrow = nm[r] ? 1.f : 0.f;
            #pragma unroll
            for (int nt = 0; nt < NTN; ++nt) {
                int c = cn + wn * WTN + nt * 8 + tig * 2;
                float v0 = acc[mi][nt][half * 2 + 0] + bias[c];
                float v1 = acc[mi][nt][half * 2 + 1] + bias[c + 1];
                if (MODE == 0) {
                    int part = c >> 8, hh = (c >> 5) & 7, dd = c & 31;
                    int b2 = r >> 11, n = r & 2047;
                    if (part == 2) {
                        size_t base = ((size_t)(b2 * NHEAD + hh) * HD + dd) * NSEQ + n;
                        g_vT[base]        = __float2bfloat16(v0);
                        g_vT[base + NSEQ] = __float2bfloat16(v1);
                    } else {
                        bf16* dst = (part == 0) ? g_q : g_k;
                        __nv_bfloat162 pv = __floats2bfloat162_rn(v0, v1);
                        *(__nv_bfloat162*)&dst[((size_t)(b2 * NHEAD + hh) * NSEQ + n) * HD + dd] = pv;
                    }
                } else if (MODE == 2) {
                    float g0 = 0.5f * v0 * (1.f + erff(v0 * 0.70710678118654752f));
                    float g1 = 0.5f * v1 * (1.f + erff(v1 * 0.70710678118654752f));
                    *(__nv_bfloat162*)&outb[(size_t)r * NT + c] = __floats2bfloat162_rn(g0, g1);
                } else {
                    float2 ex = *(const float2*)&extra[(size_t)r * NT + c];
                    *(float2*)&outf[(size_t)r * NT + c] =
                        make_float2(ex.x + v0 * mrow, ex.y + v1 * mrow);
                }
            }
        }
    }
}

// ---------------- bf16 MMA flash attention, fixed-max softmax ----------------
// block: 128 q rows, 8 warps; 16 key tiles of 128, 2-stage cp.async K/V pipeline
__global__ void __launch_bounds__(256, 2)
attn_mma(const int*   __restrict__ edge_types,
         const int*   __restrict__ node_mask,
         const float* __restrict__ ebt)
{
    extern __shared__ __align__(16) bf16 smb[];
    bf16* Qs  = smb;             // 128*40
    bf16* Ks0 = Qs  + 5120;      // 2 stages x 128*40
    bf16* Vs0 = Ks0 + 10240;     // 2 stages x 32*136
    bf16* S   = Vs0 + 8704;      // 128*136
    float* lsum = (float*)(S + 17408);  // 128
    float* nmi  = lsum + 128;           // 128
    float* tbl  = nmi + 128;            // 16

    int tid = threadIdx.x, lane = tid & 31, warp = tid >> 5;
    int gid = lane >> 2, tig = lane & 3;
    int wm = warp & 3, wn = warp >> 2;
    int bid = blockIdx.x;
    int h = bid & 7, rb = (bid >> 3) & 15, b = bid >> 7;  // h fastest: edge L2 reuse
    int r0 = rb * 128;
    const int bN = b * NSEQ;
    const float scale = 0.17677669529663687f;

    const bf16* qptr = g_q  + ((size_t)(b * NHEAD + h) * NSEQ + r0) * HD;
    const bf16* kbh  = g_k  + (size_t)(b * NHEAD + h) * NSEQ * HD;
    const bf16* vT   = g_vT + (size_t)(b * NHEAD + h) * HD * NSEQ;

    auto load_kv = [&](int kt, int st) {
        int j0 = kt * 128;
        bf16* Ksd = Ks0 + st * 5120;
        bf16* Vsd = Vs0 + st * 4352;
        #pragma unroll
        for (int i = 0; i < 2; ++i) {
            int c = tid + i * 256, row = c >> 2, off = (c & 3) * 8;
            cpasync16(&Ksd[row * 40 + off], kbh + (size_t)(j0 + row) * HD + off);
        }
        #pragma unroll
        for (int i = 0; i < 2; ++i) {
            int c = tid + i * 256, d = c >> 4, off = (c & 15) * 8;
            cpasync16(&Vsd[d * 136 + off], vT + (size_t)d * NSEQ + j0 + off);
        }
        CP_COMMIT();
    };

    load_kv(0, 0);

    #pragma unroll
    for (int i = 0; i < 2; ++i) {
        int c = tid + i * 256, row = c >> 2, off = (c & 3) * 8;
        *(uint4*)&Qs[row * 40 + off] = *(const uint4*)(qptr + (size_t)row * HD + off);
    }
    if (tid < 128) {
        lsum[tid] = 0.f;
        nmi[tid]  = node_mask[bN + r0 + tid] ? 1.f : 0.f;
    }
    if (tid < 9) tbl[tid] = ebt[tid * NHEAD + h];
    __syncthreads();

    // preload Q fragments (fixed across all key tiles)
    const uint32_t* Q32 = (const uint32_t*)Qs;
    uint32_t qa[2][2][4];
    #pragma unroll
    for (int mi = 0; mi < 2; ++mi) {
        int base = wm * 32 + mi * 16;
        #pragma unroll
        for (int ks = 0; ks < 2; ++ks) {
            qa[mi][ks][0] = Q32[(base + gid    ) * 20 + ks * 8 + tig    ];
            qa[mi][ks][1] = Q32[(base + gid + 8) * 20 + ks * 8 + tig    ];
            qa[mi][ks][2] = Q32[(base + gid    ) * 20 + ks * 8 + tig + 4];
            qa[mi][ks][3] = Q32[(base + gid + 8) * 20 + ks * 8 + tig + 4];
        }
    }
    float nmi_r[2][2];
    #pragma unroll
    for (int mi = 0; mi < 2; ++mi) {
        nmi_r[mi][0] = nmi[wm * 32 + mi * 16 + gid];
        nmi_r[mi][1] = nmi[wm * 32 + mi * 16 + gid + 8];
    }

    float oacc[4][4];
    #pragma unroll
    for (int nt = 0; nt < 4; ++nt)
        #pragma unroll
        for (int q = 0; q < 4; ++q) oacc[nt][q] = 0.f;
    int w16 = warp * 16;

    for (int kt = 0; kt < 16; ++kt) {
        int st = kt & 1, j0 = kt * 128;
        CP_WAIT0();
        __syncthreads();
        if (kt + 1 < 16) load_kv(kt + 1, st ^ 1);

        // ---- QK^T ----
        const uint32_t* K32 = (const uint32_t*)(Ks0 + st * 5120);
        float sacc[2][8][4];
        #pragma unroll
        for (int mi = 0; mi < 2; ++mi)
            #pragma unroll
            for (int nt = 0; nt < 8; ++nt)
                #pragma unroll
                for (int q = 0; q < 4; ++q) sacc[mi][nt][q] = 0.f;
        #pragma unroll
        for (int ks = 0; ks < 2; ++ks) {
            #pragma unroll
            for (int nt = 0; nt < 8; ++nt) {
                int n = wn * 64 + nt * 8 + gid;
                uint32_t b0 = K32[n * 20 + ks * 8 + tig];
                uint32_t b1 = K32[n * 20 + ks * 8 + tig + 4];
                mma16(sacc[0][nt], qa[0][ks][0], qa[0][ks][1], qa[0][ks][2], qa[0][ks][3], b0, b1);
                mma16(sacc[1][nt], qa[1][ks][0], qa[1][ks][1], qa[1][ks][2], qa[1][ks][3], b0, b1);
            }
        }

        // ---- epilogue: bias + mask + exp(max=0), write P bf16, row sums ----
        float lp[2][2] = {{0.f, 0.f}, {0.f, 0.f}};
        uint32_t* S32w = (uint32_t*)S;
        #pragma unroll
        for (int nt = 0; nt < 8; ++nt) {
            int ccol = wn * 64 + nt * 8 + tig * 2;
            int gj = j0 + ccol;
            float nj0 = node_mask[bN + gj    ] ? 1.f : 0.f;
            float nj1 = node_mask[bN + gj + 1] ? 1.f : 0.f;
            #pragma unroll
            for (int mi = 0; mi < 2; ++mi) {
                #pragma unroll
                for (int half = 0; half < 2; ++half) {
                    int rloc = wm * 32 + mi * 16 + gid + half * 8;
                    int gi = r0 + rloc;
                    int2 ee = *(const int2*)(edge_types + ((size_t)(bN + gi)) * NSEQ + gj);
                    float ni = nmi_r[mi][half];
                    bool ok0 = ((ee.x != 0) | (gi == gj    )) && (ni != 0.f) && (nj0 != 0.f);
                    bool ok1 = ((ee.y != 0) | (gi == gj + 1)) && (ni != 0.f) && (nj1 != 0.f);
                    float p0 = ok0 ? __expf(sacc[mi][nt][half * 2 + 0] * scale + tbl[ee.x]) : 0.f;
                    float p1 = ok1 ? __expf(sacc[mi][nt][half * 2 + 1] * scale + tbl[ee.y]) : 0.f;
                    lp[mi][half] += p0 + p1;
                    __nv_bfloat162 pv = __floats2bfloat162_rn(p0, p1);
                    S32w[(rloc * 136 + ccol) >> 1] = *(uint32_t*)&pv;
                }
            }
        }
        #pragma unroll
        for (int mi = 0; mi < 2; ++mi) {
            #pragma unroll
            for (int half = 0; half < 2; ++half) {
                float v = lp[mi][half];
                v += __shfl_xor_sync(0xffffffffu, v, 1);
                v += __shfl_xor_sync(0xffffffffu, v, 2);
                if (tig == 0)
                    atomicAdd(&lsum[wm * 32 + mi * 16 + gid + half * 8], v);
            }
        }
        __syncthreads();

        // ---- PV: O += P[128x128] V[128x32]; warp w -> rows w*16..+15 ----
        const uint32_t* Sr  = (const uint32_t*)S;
        const uint32_t* V32 = (const uint32_t*)(Vs0 + st * 4352);
        #pragma unroll
        for (int ks = 0; ks < 8; ++ks) {
            uint32_t a0 = Sr[(w16 + gid    ) * 68 + ks * 8 + tig    ];
            uint32_t a1 = Sr[(w16 + gid + 8) * 68 + ks * 8 + tig    ];
            uint32_t a2 = Sr[(w16 + gid    ) * 68 + ks * 8 + tig + 4];
            uint32_t a3 = Sr[(w16 + gid + 8) * 68 + ks * 8 + tig + 4];
            #pragma unroll
            for (int nt = 0; nt < 4; ++nt) {
                int d = nt * 8 + gid;
                uint32_t b0 = V32[d * 68 + ks * 8 + tig];
                uint32_t b1 = V32[d * 68 + ks * 8 + tig + 4];
                mma16(oacc[nt], a0, a1, a2, a3, b0, b1);
            }
        }
        // no trailing sync: next iter's wait+sync orders S/V buffer reuse
    }

    // ---- normalize + write bf16 [B,N,DIM] ----
    float lv0 = lsum[w16 + gid], lv1 = lsum[w16 + gid + 8];
    float inv0 = lv0 > 0.f ? 1.f / lv0 : 0.f;
    float inv1 = lv1 > 0.f ? 1.f / lv1 : 0.f;
    bf16* od = g_ao + ((size_t)(bN + r0)) * DIMD + h * HD;
    #pragma unroll
    for (int nt = 0; nt < 4; ++nt) {
        int d = nt * 8 + tig * 2;
        *(__nv_bfloat162*)&od[(size_t)(w16 + gid    ) * DIMD + d] =
            __floats2bfloat162_rn(oacc[nt][0] * inv0, oacc[nt][1] * inv0);
        *(__nv_bfloat162*)&od[(size_t)(w16 + gid + 8) * DIMD + d] =
            __floats2bfloat162_rn(oacc[nt][2] * inv1, oacc[nt][3] * inv1);
    }
}

// ---------------- launch ----------------
static void* sym_addr(const void* sym)
{
    void* p = nullptr;
    cudaGetSymbolAddress(&p, sym);
    return p;
}

extern "C" void kernel_launch(void* const* d_in, const int* in_sizes, int n_in,
                              void* d_out, int out_size)
{
    const float* x      = (const float*)d_in[0];
    const int*   etyp   = (const int*)  d_in[1];
    const int*   nmask  = (const int*)  d_in[2];
    const float* qkv_w  = (const float*)d_in[3];
    const float* qkv_b  = (const float*)d_in[4];
    const float* proj_w = (const float*)d_in[5];
    const float* proj_b = (const float*)d_in[6];
    const float* ebt    = (const float*)d_in[7];
    const float* ln1_g  = (const float*)d_in[8];
    const float* ln1_b  = (const float*)d_in[9];
    const float* ln2_g  = (const float*)d_in[10];
    const float* ln2_b  = (const float*)d_in[11];
    const float* ffn_w1 = (const float*)d_in[12];
    const float* ffn_b1 = (const float*)d_in[13];
    const float* ffn_w2 = (const float*)d_in[14];
    const float* ffn_b2 = (const float*)d_in[15];
    float* out = (float*)d_out;

    bf16*  ph    = (bf16*) sym_addr(g_h);
    bf16*  pao   = (bf16*) sym_addr(g_ao);
    float* px1   = (float*)sym_addr(g_x1);
    bf16*  ph2   = (bf16*) sym_addr(g_h2);
    bf16*  pmid  = (bf16*) sym_addr(g_mid);
    bf16*  pwqkv = (bf16*) sym_addr(g_wqkv);
    bf16*  pwproj= (bf16*) sym_addr(g_wproj);
    bf16*  pwf1  = (bf16*) sym_addr(g_wf1);
    bf16*  pwf2  = (bf16*) sym_addr(g_wf2);

    const int ATTN_SMEM = 84032;
    cudaFuncSetAttribute(attn_mma, cudaFuncAttributeMaxDynamicSharedMemorySize, ATTN_SMEM);

    // 0) weight conversion (fp32 [K][N] -> bf16 [N][K])
    wconv<<<(DIMD*3*DIMD + 255)/256, 256>>>(qkv_w,  pwqkv,  DIMD, 3*DIMD);
    wconv<<<(DIMD*DIMD   + 255)/256, 256>>>(proj_w, pwproj, DIMD, DIMD);
    wconv<<<(DIMD*FFD    + 255)/256, 256>>>(ffn_w1, pwf1,   DIMD, FFD);
    wconv<<<(FFD*DIMD    + 255)/256, 256>>>(ffn_w2, pwf2,   FFD,  DIMD);

    // 1) LN1 -> bf16
    ln_kernel<<<ROWS, 256>>>(x, ln1_g, ln1_b, ph);
    // 2) QKV GEMM + scatter (q,k normal; v transposed)
    mma_gemm<128, 128, DIMD, 3*DIMD, 0><<<dim3(6, 32), 256>>>(
        ph, pwqkv, qkv_b, nullptr, nullptr, nullptr, nullptr);
    // 3) attention
    attn_mma<<<BNUM * NHEAD * (NSEQ / 128), 256, ATTN_SMEM>>>(etyp, nmask, ebt);
    // 4) proj + residual + node mask -> x1 (fp32)
    mma_gemm<64, 64, DIMD, DIMD, 1><<<dim3(4, 64), 256>>>(
        pao, pwproj, proj_b, x, nmask, px1, nullptr);
    // 5) LN2 -> bf16
    ln_kernel<<<ROWS, 256>>>(px1, ln2_g, ln2_b, ph2);
    // 6) FFN1 + exact GELU -> bf16 mid
    mma_gemm<128, 128, DIMD, FFD, 2><<<dim3(8, 32), 256>>>(
        ph2, pwf1, ffn_b1, nullptr, nullptr, nullptr, pmid);
    // 7) FFN2 + node mask + residual -> out (fp32)
    mma_gemm<64, 64, FFD, DIMD, 3><<<dim3(4, 64), 256>>>(
        pmid, pwf2, ffn_b2, px1, nmask, out, nullptr);
}

// round 4
// speedup vs baseline: 5.5688x; 1.4362x over previous
#include <cuda_runtime.h>
#include <cuda_bf16.h>
#include <math.h>
#include <stdint.h>

#define BNUM 2
#define NSEQ 2048
#define DIMD 256
#define NHEAD 8
#define HD 32
#define FFD 1024
#define ROWS (BNUM*NSEQ)   // 4096

typedef __nv_bfloat16 bf16;

// scale * log2(e), folded into Q weights/bias so epilogue uses ex2 directly
#define QSCALE (0.17677669529663687f * 1.4426950408889634f)
#define LOG2E  1.4426950408889634f

// ---------------- scratch (device globals, no allocation) ----------------
__device__ bf16  g_h  [ROWS*DIMD];
__device__ bf16  g_q  [BNUM*NHEAD*NSEQ*HD];
__device__ bf16  g_k  [BNUM*NHEAD*NSEQ*HD];
__device__ bf16  g_vT [BNUM*NHEAD*HD*NSEQ];   // [b][h][d][n]
__device__ bf16  g_ao [ROWS*DIMD];
__device__ float g_x1 [ROWS*DIMD];
__device__ bf16  g_h2 [ROWS*DIMD];
__device__ bf16  g_mid[ROWS*FFD];
__device__ uint8_t g_code[(size_t)BNUM*NSEQ*NSEQ];   // 0 = masked, else edge_type+1
__device__ bf16  g_wqkv [3*DIMD*DIMD];  // [768][256]  (n-major, k contiguous)
__device__ bf16  g_wproj[DIMD*DIMD];    // [256][256]
__device__ bf16  g_wf1  [FFD*DIMD];     // [1024][256]
__device__ bf16  g_wf2  [DIMD*FFD];     // [256][1024]

// ---------------- helpers ----------------
__device__ __forceinline__ void cpasync16(void* sdst, const void* gsrc){
    unsigned s = (unsigned)__cvta_generic_to_shared(sdst);
    asm volatile("cp.async.cg.shared.global [%0], [%1], 16;" :: "r"(s), "l"(gsrc));
}
#define CP_COMMIT() asm volatile("cp.async.commit_group;")
#define CP_WAIT0()  asm volatile("cp.async.wait_group 0;")

__device__ __forceinline__ void mma16(float* c,
    uint32_t a0, uint32_t a1, uint32_t a2, uint32_t a3,
    uint32_t b0, uint32_t b1)
{
    asm volatile("mma.sync.aligned.m16n8k16.row.col.f32.bf16.bf16.f32 "
        "{%0,%1,%2,%3}, {%4,%5,%6,%7}, {%8,%9}, {%0,%1,%2,%3};"
        : "+f"(c[0]), "+f"(c[1]), "+f"(c[2]), "+f"(c[3])
        : "r"(a0), "r"(a1), "r"(a2), "r"(a3), "r"(b0), "r"(b1));
}
__device__ __forceinline__ float fexp2(float x){
    float y; asm("ex2.approx.f32 %0, %1;" : "=f"(y) : "f"(x)); return y;
}

// ---------------- fused weight convert (tiled transpose, coalesced) ----------
// W[k][n] fp32 -> Wt[n][k] bf16.  Q columns (n<256 of qkv) scaled by QSCALE.
__global__ void __launch_bounds__(256)
wconv_all(const float* __restrict__ w_qkv, const float* __restrict__ w_proj,
          const float* __restrict__ w_f1,  const float* __restrict__ w_f2)
{
    __shared__ float tile[32][33];
    int id = blockIdx.x;
    const float* W; bf16* Wt; int K, N; bool qs = false;
    if (id < 192)      { W = w_qkv;  Wt = g_wqkv;  K = 256;  N = 768;  qs = true; }
    else if (id < 256) { id -= 192; W = w_proj; Wt = g_wproj; K = 256;  N = 256; }
    else if (id < 512) { id -= 256; W = w_f1;   Wt = g_wf1;   K = 256;  N = 1024; }
    else               { id -= 512; W = w_f2;   Wt = g_wf2;   K = 1024; N = 256; }
    int tn = id % (N / 32), tk = id / (N / 32);
    int tx = threadIdx.x & 31, ty = threadIdx.x >> 5;

    #pragma unroll
    for (int r = 0; r < 4; ++r)
        tile[ty + r * 8][tx] = W[(size_t)(tk * 32 + ty + r * 8) * N + tn * 32 + tx];
    __syncthreads();
    float mul = (qs && tn < 8) ? QSCALE : 1.f;
    #pragma unroll
    for (int r = 0; r < 4; ++r) {
        int n = tn * 32 + ty + r * 8;
        Wt[(size_t)n * K + tk * 32 + tx] = __float2bfloat16(tile[tx][ty + r * 8] * mul);
    }
}

// ---------------- edge code precompute ----------------
__global__ void __launch_bounds__(256)
edge_code_kernel(const int* __restrict__ et, const int* __restrict__ nm,
                 uint8_t* __restrict__ code)
{
    int i = blockIdx.x, b = blockIdx.y;
    int bN = b * NSEQ;
    int nmi = nm[bN + i];
    const int* er = et + (size_t)(bN + i) * NSEQ;
    uint8_t* cr = code + (size_t)(bN + i) * NSEQ;
    for (int j = threadIdx.x * 4; j < NSEQ; j += 1024) {
        int4 e = *(const int4*)(er + j);
        int4 m = *(const int4*)(nm + bN + j);
        uchar4 c;
        c.x = (nmi && m.x && (e.x != 0 || i == j    )) ? (uint8_t)(e.x + 1) : 0;
        c.y = (nmi && m.y && (e.y != 0 || i == j + 1)) ? (uint8_t)(e.y + 1) : 0;
        c.z = (nmi && m.z && (e.z != 0 || i == j + 2)) ? (uint8_t)(e.z + 1) : 0;
        c.w = (nmi && m.w && (e.w != 0 || i == j + 3)) ? (uint8_t)(e.w + 1) : 0;
        *(uchar4*)(cr + j) = c;
    }
}

// ---------------- LayerNorm: one block per row of 256, bf16 out ----------------
__global__ void ln_kernel(const float* __restrict__ x,
                          const float* __restrict__ g,
                          const float* __restrict__ b,
                          bf16* __restrict__ y)
{
    int row = blockIdx.x;
    int t   = threadIdx.x;
    float v = x[(size_t)row * DIMD + t];

    __shared__ float red[8];
    __shared__ float stat[2];

    float s = v;
    #pragma unroll
    for (int o = 16; o > 0; o >>= 1) s += __shfl_xor_sync(0xffffffffu, s, o);
    if ((t & 31) == 0) red[t >> 5] = s;
    __syncthreads();
    if (t < 32) {
        float r = (t < 8) ? red[t] : 0.f;
        #pragma unroll
        for (int o = 4; o > 0; o >>= 1) r += __shfl_xor_sync(0xffffffffu, r, o);
        if (t == 0) stat[0] = r * (1.0f / DIMD);
    }
    __syncthreads();
    float mu = stat[0];
    float d  = v - mu;

    float s2 = d * d;
    #pragma unroll
    for (int o = 16; o > 0; o >>= 1) s2 += __shfl_xor_sync(0xffffffffu, s2, o);
    if ((t & 31) == 0) red[t >> 5] = s2;
    __syncthreads();
    if (t < 32) {
        float r = (t < 8) ? red[t] : 0.f;
        #pragma unroll
        for (int o = 4; o > 0; o >>= 1) r += __shfl_xor_sync(0xffffffffu, r, o);
        if (t == 0) stat[1] = rsqrtf(r * (1.0f / DIMD) + 1e-5f);
    }
    __syncthreads();
    y[(size_t)row * DIMD + t] = __float2bfloat16(d * stat[1] * g[t] + b[t]);
}

// ---------------- bf16 MMA GEMM, 2-stage cp.async pipeline ----------------
template<int BM, int BN, int KD, int NT, int MODE>
__global__ void __launch_bounds__(256, 2)
mma_gemm(const bf16* __restrict__ A, const bf16* __restrict__ Wt,
         const float* __restrict__ bias, const float* __restrict__ extra,
         const int* __restrict__ nm, float* __restrict__ outf, bf16* __restrict__ outb)
{
    constexpr int WM  = BM / 32;
    constexpr int WN  = 8 / WM;
    constexpr int WTN = BN / WN;
    constexpr int NTN = WTN / 8;
    constexpr int CA  = (BM * 32 / 8) / 256;
    constexpr int CB  = (BN * 32 / 8) / 256;

    __shared__ __align__(16) bf16 As[2][BM * 40];
    __shared__ __align__(16) bf16 Bs[2][BN * 40];

    int t = threadIdx.x, lane = t & 31, warp = t >> 5;
    int gid = lane >> 2, tig = lane & 3;
    int wm = warp % WM, wn = warp / WM;
    int rm = blockIdx.y * BM, cn = blockIdx.x * BN;
    const bf16* Ag = A  + (size_t)rm * KD;
    const bf16* Bg = Wt + (size_t)cn * KD;

    float acc[2][NTN][4];
    #pragma unroll
    for (int mi = 0; mi < 2; ++mi)
        #pragma unroll
        for (int nt = 0; nt < NTN; ++nt)
            #pragma unroll
            for (int q = 0; q < 4; ++q) acc[mi][nt][q] = 0.f;

    auto load_stage = [&](int k0, int st) {
        #pragma unroll
        for (int i = 0; i < CA; ++i) {
            int c = t + i * 256, row = c >> 2, off = (c & 3) * 8;
            cpasync16(&As[st][row * 40 + off], Ag + (size_t)row * KD + k0 + off);
        }
        #pragma unroll
        for (int i = 0; i < CB; ++i) {
            int c = t + i * 256, row = c >> 2, off = (c & 3) * 8;
            cpasync16(&Bs[st][row * 40 + off], Bg + (size_t)row * KD + k0 + off);
        }
        CP_COMMIT();
    };

    load_stage(0, 0);
    for (int k0 = 0; k0 < KD; k0 += 32) {
        int st = (k0 >> 5) & 1;
        CP_WAIT0();
        __syncthreads();
        if (k0 + 32 < KD) load_stage(k0 + 32, st ^ 1);

        const uint32_t* A32 = (const uint32_t*)As[st];
        const uint32_t* B32 = (const uint32_t*)Bs[st];
        #pragma unroll
        for (int ks = 0; ks < 2; ++ks) {
            uint32_t af[2][4];
            #pragma unroll
            for (int mi = 0; mi < 2; ++mi) {
                int base = wm * 32 + mi * 16;
                af[mi][0] = A32[(base + gid    ) * 20 + ks * 8 + tig    ];
                af[mi][1] = A32[(base + gid + 8) * 20 + ks * 8 + tig    ];
                af[mi][2] = A32[(base + gid    ) * 20 + ks * 8 + tig + 4];
                af[mi][3] = A32[(base + gid + 8) * 20 + ks * 8 + tig + 4];
            }
            #pragma unroll
            for (int nt = 0; nt < NTN; ++nt) {
                int n = wn * WTN + nt * 8 + gid;
                uint32_t b0 = B32[n * 20 + ks * 8 + tig];
                uint32_t b1 = B32[n * 20 + ks * 8 + tig + 4];
                mma16(acc[0][nt], af[0][0], af[0][1], af[0][2], af[0][3], b0, b1);
                mma16(acc[1][nt], af[1][0], af[1][1], af[1][2], af[1][3], b0, b1);
            }
        }
    }
    __syncthreads();

    // ---- epilogue ----
    #pragma unroll
    for (int mi = 0; mi < 2; ++mi) {
        #pragma unroll
        for (int half = 0; half < 2; ++half) {
            int r = rm + wm * 32 + mi * 16 + gid + half * 8;
            float mrow = 0.f;
            if (MODE == 1 || MODE == 3) mrow = nm[r] ? 1.f : 0.f;
            #pragma unroll
            for (int nt = 0; nt < NTN; ++nt) {
                int c = cn + wn * WTN + nt * 8 + tig * 2;
                float bmul = (MODE == 0 && c < DIMD) ? QSCALE : 1.f;
                float v0 = acc[mi][nt][half * 2 + 0] + bias[c] * bmul;
                float v1 = acc[mi][nt][half * 2 + 1] + bias[c + 1] * bmul;
                if (MODE == 0) {
                    int part = c >> 8, hh = (c >> 5) & 7, dd = c & 31;
                    int b2 = r >> 11, n = r & 2047;
                    if (part == 2) {
                        size_t base = ((size_t)(b2 * NHEAD + hh) * HD + dd) * NSEQ + n;
                        g_vT[base]        = __float2bfloat16(v0);
                        g_vT[base + NSEQ] = __float2bfloat16(v1);
                    } else {
                        bf16* dst = (part == 0) ? g_q : g_k;
                        __nv_bfloat162 pv = __floats2bfloat162_rn(v0, v1);
                        *(__nv_bfloat162*)&dst[((size_t)(b2 * NHEAD + hh) * NSEQ + n) * HD + dd] = pv;
                    }
                } else if (MODE == 2) {
                    float g0 = 0.5f * v0 * (1.f + erff(v0 * 0.70710678118654752f));
                    float g1 = 0.5f * v1 * (1.f + erff(v1 * 0.70710678118654752f));
                    *(__nv_bfloat162*)&outb[(size_t)r * NT + c] = __floats2bfloat162_rn(g0, g1);
                } else {
                    float2 ex = *(const float2*)&extra[(size_t)r * NT + c];
                    *(float2*)&outf[(size_t)r * NT + c] =
                        make_float2(ex.x + v0 * mrow, ex.y + v1 * mrow);
                }
            }
        }
    }
}

// ---------------- bf16 MMA flash attention, fixed-max softmax ----------------
// Q pre-scaled by scale*log2e; edge code precomputed; p = ex2(s + tbl2[code]).
__global__ void __launch_bounds__(256, 2)
attn_mma(const float* __restrict__ ebt)
{
    extern __shared__ __align__(16) bf16 smb[];
    bf16* Qs  = smb;             // 128*40
    bf16* Ks0 = Qs  + 5120;      // 2 stages x 128*40
    bf16* Vs0 = Ks0 + 10240;     // 2 stages x 32*136
    bf16* S   = Vs0 + 8704;      // 128*136
    float* lsum2 = (float*)(S + 17408);  // [2][128] per wn
    float* tbl2  = lsum2 + 256;          // 16

    int tid = threadIdx.x, lane = tid & 31, warp = tid >> 5;
    int gid = lane >> 2, tig = lane & 3;
    int wm = warp & 3, wn = warp >> 2;
    int bid = blockIdx.x;
    int h = bid & 7, rb = (bid >> 3) & 15, b = bid >> 7;  // h fastest: code L2 reuse
    int r0 = rb * 128;
    const int bN = b * NSEQ;

    const bf16* qptr = g_q  + ((size_t)(b * NHEAD + h) * NSEQ + r0) * HD;
    const bf16* kbh  = g_k  + (size_t)(b * NHEAD + h) * NSEQ * HD;
    const bf16* vT   = g_vT + (size_t)(b * NHEAD + h) * HD * NSEQ;

    auto load_kv = [&](int kt, int st) {
        int j0 = kt * 128;
        bf16* Ksd = Ks0 + st * 5120;
        bf16* Vsd = Vs0 + st * 4352;
        #pragma unroll
        for (int i = 0; i < 2; ++i) {
            int c = tid + i * 256, row = c >> 2, off = (c & 3) * 8;
            cpasync16(&Ksd[row * 40 + off], kbh + (size_t)(j0 + row) * HD + off);
        }
        #pragma unroll
        for (int i = 0; i < 2; ++i) {
            int c = tid + i * 256, d = c >> 4, off = (c & 15) * 8;
            cpasync16(&Vsd[d * 136 + off], vT + (size_t)d * NSEQ + j0 + off);
        }
        CP_COMMIT();
    };

    load_kv(0, 0);

    #pragma unroll
    for (int i = 0; i < 2; ++i) {
        int c = tid + i * 256, row = c >> 2, off = (c & 3) * 8;
        *(uint4*)&Qs[row * 40 + off] = *(const uint4*)(qptr + (size_t)row * HD + off);
    }
    if (tid < 16)
        tbl2[tid] = (tid == 0) ? -30000.f
                  : (tid < 10 ? ebt[(tid - 1) * NHEAD + h] * LOG2E : 0.f);
    __syncthreads();

    // preload Q fragments
    const uint32_t* Q32 = (const uint32_t*)Qs;
    uint32_t qa[2][2][4];
    #pragma unroll
    for (int mi = 0; mi < 2; ++mi) {
        int base = wm * 32 + mi * 16;
        #pragma unroll
        for (int ks = 0; ks < 2; ++ks) {
            qa[mi][ks][0] = Q32[(base + gid    ) * 20 + ks * 8 + tig    ];
            qa[mi][ks][1] = Q32[(base + gid + 8) * 20 + ks * 8 + tig    ];
            qa[mi][ks][2] = Q32[(base + gid    ) * 20 + ks * 8 + tig + 4];
            qa[mi][ks][3] = Q32[(base + gid + 8) * 20 + ks * 8 + tig + 4];
        }
    }

    float oacc[4][4];
    #pragma unroll
    for (int nt = 0; nt < 4; ++nt)
        #pragma unroll
        for (int q = 0; q < 4; ++q) oacc[nt][q] = 0.f;
    float lp[2][2] = {{0.f, 0.f}, {0.f, 0.f}};
    int w16 = warp * 16;

    for (int kt = 0; kt < 16; ++kt) {
        int st = kt & 1, j0 = kt * 128;
        CP_WAIT0();
        __syncthreads();
        if (kt + 1 < 16) load_kv(kt + 1, st ^ 1);

        // ---- QK^T ----
        const uint32_t* K32 = (const uint32_t*)(Ks0 + st * 5120);
        float sacc[2][8][4];
        #pragma unroll
        for (int mi = 0; mi < 2; ++mi)
            #pragma unroll
            for (int nt = 0; nt < 8; ++nt)
                #pragma unroll
                for (int q = 0; q < 4; ++q) sacc[mi][nt][q] = 0.f;
        #pragma unroll
        for (int ks = 0; ks < 2; ++ks) {
            #pragma unroll
            for (int nt = 0; nt < 8; ++nt) {
                int n = wn * 64 + nt * 8 + gid;
                uint32_t b0 = K32[n * 20 + ks * 8 + tig];
                uint32_t b1 = K32[n * 20 + ks * 8 + tig + 4];
                mma16(sacc[0][nt], qa[0][ks][0], qa[0][ks][1], qa[0][ks][2], qa[0][ks][3], b0, b1);
                mma16(sacc[1][nt], qa[1][ks][0], qa[1][ks][1], qa[1][ks][2], qa[1][ks][3], b0, b1);
            }
        }

        // ---- epilogue: p = ex2(s + tbl2[code]), write P bf16, row sums ----
        uint32_t* S32w = (uint32_t*)S;
        #pragma unroll
        for (int mi = 0; mi < 2; ++mi) {
            #pragma unroll
            for (int half = 0; half < 2; ++half) {
                int rloc = wm * 32 + mi * 16 + gid + half * 8;
                const uint8_t* crow = g_code +
                    (size_t)(bN + r0 + rloc) * NSEQ + j0 + wn * 64 + tig * 2;
                float lacc = 0.f;
                #pragma unroll
                for (int nt = 0; nt < 8; ++nt) {
                    unsigned short cc = *(const unsigned short*)(crow + nt * 8);
                    float p0 = fexp2(sacc[mi][nt][half * 2 + 0] + tbl2[cc & 0xff]);
                    float p1 = fexp2(sacc[mi][nt][half * 2 + 1] + tbl2[cc >> 8]);
                    lacc += p0 + p1;
                    __nv_bfloat162 pv = __floats2bfloat162_rn(p0, p1);
                    S32w[(rloc * 136 + wn * 64 + nt * 8 + tig * 2) >> 1] = *(uint32_t*)&pv;
                }
                lp[mi][half] += lacc;
            }
        }
        __syncthreads();

        // ---- PV: O += P[128x128] V[128x32]; warp w -> rows w*16..+15 ----
        const uint32_t* Sr  = (const uint32_t*)S;
        const uint32_t* V32 = (const uint32_t*)(Vs0 + st * 4352);
        #pragma unroll
        for (int ks = 0; ks < 8; ++ks) {
            uint32_t a0 = Sr[(w16 + gid    ) * 68 + ks * 8 + tig    ];
            uint32_t a1 = Sr[(w16 + gid + 8) * 68 + ks * 8 + tig    ];
            uint32_t a2 = Sr[(w16 + gid    ) * 68 + ks * 8 + tig + 4];
            uint32_t a3 = Sr[(w16 + gid + 8) * 68 + ks * 8 + tig + 4];
            #pragma unroll
            for (int nt = 0; nt < 4; ++nt) {
                int d = nt * 8 + gid;
                uint32_t b0 = V32[d * 68 + ks * 8 + tig];
                uint32_t b1 = V32[d * 68 + ks * 8 + tig + 4];
                mma16(oacc[nt], a0, a1, a2, a3, b0, b1);
            }
        }
    }

    // ---- row-sum finalize (hoisted out of tile loop) ----
    #pragma unroll
    for (int mi = 0; mi < 2; ++mi) {
        #pragma unroll
        for (int half = 0; half < 2; ++half) {
            float v = lp[mi][half];
            v += __shfl_xor_sync(0xffffffffu, v, 1);
            v += __shfl_xor_sync(0xffffffffu, v, 2);
            if (tig == 0)
                lsum2[wn * 128 + wm * 32 + mi * 16 + gid + half * 8] = v;
        }
    }
    __syncthreads();

    // ---- normalize + write bf16 [B,N,DIM] ----
    float lv0 = lsum2[w16 + gid] + lsum2[128 + w16 + gid];
    float lv1 = lsum2[w16 + gid + 8] + lsum2[128 + w16 + gid + 8];
    float inv0 = lv0 > 0.f ? 1.f / lv0 : 0.f;
    float inv1 = lv1 > 0.f ? 1.f / lv1 : 0.f;
    bf16* od = g_ao + ((size_t)(bN + r0)) * DIMD + h * HD;
    #pragma unroll
    for (int nt = 0; nt < 4; ++nt) {
        int d = nt * 8 + tig * 2;
        *(__nv_bfloat162*)&od[(size_t)(w16 + gid    ) * DIMD + d] =
            __floats2bfloat162_rn(oacc[nt][0] * inv0, oacc[nt][1] * inv0);
        *(__nv_bfloat162*)&od[(size_t)(w16 + gid + 8) * DIMD + d] =
            __floats2bfloat162_rn(oacc[nt][2] * inv1, oacc[nt][3] * inv1);
    }
}

// ---------------- launch ----------------
static void* sym_addr(const void* sym)
{
    void* p = nullptr;
    cudaGetSymbolAddress(&p, sym);
    return p;
}

extern "C" void kernel_launch(void* const* d_in, const int* in_sizes, int n_in,
                              void* d_out, int out_size)
{
    const float* x      = (const float*)d_in[0];
    const int*   etyp   = (const int*)  d_in[1];
    const int*   nmask  = (const int*)  d_in[2];
    const float* qkv_w  = (const float*)d_in[3];
    const float* qkv_b  = (const float*)d_in[4];
    const float* proj_w = (const float*)d_in[5];
    const float* proj_b = (const float*)d_in[6];
    const float* ebt    = (const float*)d_in[7];
    const float* ln1_g  = (const float*)d_in[8];
    const float* ln1_b  = (const float*)d_in[9];
    const float* ln2_g  = (const float*)d_in[10];
    const float* ln2_b  = (const float*)d_in[11];
    const float* ffn_w1 = (const float*)d_in[12];
    const float* ffn_b1 = (const float*)d_in[13];
    const float* ffn_w2 = (const float*)d_in[14];
    const float* ffn_b2 = (const float*)d_in[15];
    float* out = (float*)d_out;

    bf16*  ph    = (bf16*) sym_addr(g_h);
    bf16*  pao   = (bf16*) sym_addr(g_ao);
    float* px1   = (float*)sym_addr(g_x1);
    bf16*  ph2   = (bf16*) sym_addr(g_h2);
    bf16*  pmid  = (bf16*) sym_addr(g_mid);
    bf16*  pwqkv = (bf16*) sym_addr(g_wqkv);
    bf16*  pwproj= (bf16*) sym_addr(g_wproj);
    bf16*  pwf1  = (bf16*) sym_addr(g_wf1);
    bf16*  pwf2  = (bf16*) sym_addr(g_wf2);
    uint8_t* pcode = (uint8_t*)sym_addr(g_code);

    const int ATTN_SMEM = 84032;
    cudaFuncSetAttribute(attn_mma, cudaFuncAttributeMaxDynamicSharedMemorySize, ATTN_SMEM);

    // 0) fused weight conversion + edge code precompute
    wconv_all<<<768, 256>>>(qkv_w, proj_w, ffn_w1, ffn_w2);
    edge_code_kernel<<<dim3(NSEQ, BNUM), 256>>>(etyp, nmask, pcode);

    // 1) LN1 -> bf16
    ln_kernel<<<ROWS, 256>>>(x, ln1_g, ln1_b, ph);
    // 2) QKV GEMM + scatter (q scaled; k normal; v transposed)
    mma_gemm<128, 128, DIMD, 3*DIMD, 0><<<dim3(6, 32), 256>>>(
        ph, pwqkv, qkv_b, nullptr, nullptr, nullptr, nullptr);
    // 3) attention
    attn_mma<<<BNUM * NHEAD * (NSEQ / 128), 256, ATTN_SMEM>>>(ebt);
    // 4) proj + residual + node mask -> x1 (fp32)
    mma_gemm<64, 64, DIMD, DIMD, 1><<<dim3(4, 64), 256>>>(
        pao, pwproj, proj_b, x, nmask, px1, nullptr);
    // 5) LN2 -> bf16
    ln_kernel<<<ROWS, 256>>>(px1, ln2_g, ln2_b, ph2);
    // 6) FFN1 + exact GELU -> bf16 mid
    mma_gemm<128, 128, DIMD, FFD, 2><<<dim3(8, 32), 256>>>(
        ph2, pwf1, ffn_b1, nullptr, nullptr, nullptr, pmid);
    // 7) FFN2 + node mask + residual -> out (fp32)
    mma_gemm<64, 64, FFD, DIMD, 3><<<dim3(4, 64), 256>>>(
        pmid, pwf2, ffn_b2, px1, nmask, out, nullptr);
}

// round 5
// speedup vs baseline: 6.0189x; 1.0808x over previous
#include <cuda_runtime.h>
#include <cuda_bf16.h>
#include <math.h>
#include <stdint.h>

#define BNUM 2
#define NSEQ 2048
#define DIMD 256
#define NHEAD 8
#define HD 32
#define FFD 1024
#define ROWS (BNUM*NSEQ)   // 4096

typedef __nv_bfloat16 bf16;

#define QSCALE (0.17677669529663687f * 1.4426950408889634f)
#define LOG2E  1.4426950408889634f

// ---------------- scratch (device globals, no allocation) ----------------
__device__ bf16  g_h  [ROWS*DIMD];
__device__ bf16  g_q  [BNUM*NHEAD*NSEQ*HD];
__device__ bf16  g_k  [BNUM*NHEAD*NSEQ*HD];
__device__ bf16  g_vT [BNUM*NHEAD*HD*NSEQ];   // [b][h][d][n]
__device__ bf16  g_ao [ROWS*DIMD];
__device__ float g_x1 [ROWS*DIMD];
__device__ bf16  g_h2 [ROWS*DIMD];
__device__ bf16  g_mid[ROWS*FFD];
__device__ uint8_t g_code[(size_t)BNUM*NSEQ*NSEQ];   // 0 = masked, else edge_type+1
__device__ bf16  g_wqkv [3*DIMD*DIMD];
__device__ bf16  g_wproj[DIMD*DIMD];
__device__ bf16  g_wf1  [FFD*DIMD];
__device__ bf16  g_wf2  [DIMD*FFD];

// ---------------- helpers ----------------
__device__ __forceinline__ void cpasync16(void* sdst, const void* gsrc){
    unsigned s = (unsigned)__cvta_generic_to_shared(sdst);
    asm volatile("cp.async.cg.shared.global [%0], [%1], 16;" :: "r"(s), "l"(gsrc));
}
#define CP_COMMIT() asm volatile("cp.async.commit_group;")
template<int N> __device__ __forceinline__ void cp_wait(){
    asm volatile("cp.async.wait_group %0;" :: "n"(N));
}

__device__ __forceinline__ void mma16(float* c,
    uint32_t a0, uint32_t a1, uint32_t a2, uint32_t a3,
    uint32_t b0, uint32_t b1)
{
    asm volatile("mma.sync.aligned.m16n8k16.row.col.f32.bf16.bf16.f32 "
        "{%0,%1,%2,%3}, {%4,%5,%6,%7}, {%8,%9}, {%0,%1,%2,%3};"
        : "+f"(c[0]), "+f"(c[1]), "+f"(c[2]), "+f"(c[3])
        : "r"(a0), "r"(a1), "r"(a2), "r"(a3), "r"(b0), "r"(b1));
}
__device__ __forceinline__ float fexp2(float x){
    float y; asm("ex2.approx.f32 %0, %1;" : "=f"(y) : "f"(x)); return y;
}

// ---------------- fused weight convert (tiled transpose, coalesced) ----------
__global__ void __launch_bounds__(256)
wconv_all(const float* __restrict__ w_qkv, const float* __restrict__ w_proj,
          const float* __restrict__ w_f1,  const float* __restrict__ w_f2)
{
    __shared__ float tile[32][33];
    int id = blockIdx.x;
    const float* W; bf16* Wt; int K, N; bool qs = false;
    if (id < 192)      { W = w_qkv;  Wt = g_wqkv;  K = 256;  N = 768;  qs = true; }
    else if (id < 256) { id -= 192; W = w_proj; Wt = g_wproj; K = 256;  N = 256; }
    else if (id < 512) { id -= 256; W = w_f1;   Wt = g_wf1;   K = 256;  N = 1024; }
    else               { id -= 512; W = w_f2;   Wt = g_wf2;   K = 1024; N = 256; }
    int tn = id % (N / 32), tk = id / (N / 32);
    int tx = threadIdx.x & 31, ty = threadIdx.x >> 5;

    #pragma unroll
    for (int r = 0; r < 4; ++r)
        tile[ty + r * 8][tx] = W[(size_t)(tk * 32 + ty + r * 8) * N + tn * 32 + tx];
    __syncthreads();
    float mul = (qs && tn < 8) ? QSCALE : 1.f;
    #pragma unroll
    for (int r = 0; r < 4; ++r) {
        int n = tn * 32 + ty + r * 8;
        Wt[(size_t)n * K + tk * 32 + tx] = __float2bfloat16(tile[tx][ty + r * 8] * mul);
    }
}

// ---------------- edge code precompute ----------------
__global__ void __launch_bounds__(256)
edge_code_kernel(const int* __restrict__ et, const int* __restrict__ nm,
                 uint8_t* __restrict__ code)
{
    int i = blockIdx.x, b = blockIdx.y;
    int bN = b * NSEQ;
    int nmi = nm[bN + i];
    const int* er = et + (size_t)(bN + i) * NSEQ;
    uint8_t* cr = code + (size_t)(bN + i) * NSEQ;
    for (int j = threadIdx.x * 4; j < NSEQ; j += 1024) {
        int4 e = *(const int4*)(er + j);
        int4 m = *(const int4*)(nm + bN + j);
        uchar4 c;
        c.x = (nmi && m.x && (e.x != 0 || i == j    )) ? (uint8_t)(e.x + 1) : 0;
        c.y = (nmi && m.y && (e.y != 0 || i == j + 1)) ? (uint8_t)(e.y + 1) : 0;
        c.z = (nmi && m.z && (e.z != 0 || i == j + 2)) ? (uint8_t)(e.z + 1) : 0;
        c.w = (nmi && m.w && (e.w != 0 || i == j + 3)) ? (uint8_t)(e.w + 1) : 0;
        *(uchar4*)(cr + j) = c;
    }
}

// ---------------- LayerNorm ----------------
__global__ void ln_kernel(const float* __restrict__ x,
                          const float* __restrict__ g,
                          const float* __restrict__ b,
                          bf16* __restrict__ y)
{
    int row = blockIdx.x;
    int t   = threadIdx.x;
    float v = x[(size_t)row * DIMD + t];

    __shared__ float red[8];
    __shared__ float stat[2];

    float s = v;
    #pragma unroll
    for (int o = 16; o > 0; o >>= 1) s += __shfl_xor_sync(0xffffffffu, s, o);
    if ((t & 31) == 0) red[t >> 5] = s;
    __syncthreads();
    if (t < 32) {
        float r = (t < 8) ? red[t] : 0.f;
        #pragma unroll
        for (int o = 4; o > 0; o >>= 1) r += __shfl_xor_sync(0xffffffffu, r, o);
        if (t == 0) stat[0] = r * (1.0f / DIMD);
    }
    __syncthreads();
    float mu = stat[0];
    float d  = v - mu;

    float s2 = d * d;
    #pragma unroll
    for (int o = 16; o > 0; o >>= 1) s2 += __shfl_xor_sync(0xffffffffu, s2, o);
    if ((t & 31) == 0) red[t >> 5] = s2;
    __syncthreads();
    if (t < 32) {
        float r = (t < 8) ? red[t] : 0.f;
        #pragma unroll
        for (int o = 4; o > 0; o >>= 1) r += __shfl_xor_sync(0xffffffffu, r, o);
        if (t == 0) stat[1] = rsqrtf(r * (1.0f / DIMD) + 1e-5f);
    }
    __syncthreads();
    y[(size_t)row * DIMD + t] = __float2bfloat16(d * stat[1] * g[t] + b[t]);
}

// ---------------- bf16 MMA GEMM, 3-stage cp.async pipeline ----------------
template<int BM, int BN, int KD, int NT, int MODE>
__global__ void __launch_bounds__(256, 2)
mma_gemm(const bf16* __restrict__ A, const bf16* __restrict__ Wt,
         const float* __restrict__ bias, const float* __restrict__ extra,
         const int* __restrict__ nm, float* __restrict__ outf, bf16* __restrict__ outb)
{
    constexpr int WM  = BM / 32;
    constexpr int WN  = 8 / WM;
    constexpr int WTN = BN / WN;
    constexpr int NTN = WTN / 8;
    constexpr int CA  = (BM * 32 / 8) / 256;
    constexpr int CB  = (BN * 32 / 8) / 256;
    constexpr int NK  = KD / 32;

    extern __shared__ __align__(16) bf16 gsm[];
    bf16* As = gsm;                 // [3][BM*40]
    bf16* Bs = gsm + 3 * BM * 40;   // [3][BN*40]

    int t = threadIdx.x, lane = t & 31, warp = t >> 5;
    int gid = lane >> 2, tig = lane & 3;
    int wm = warp % WM, wn = warp / WM;
    int rm = blockIdx.y * BM, cn = blockIdx.x * BN;
    const bf16* Ag = A  + (size_t)rm * KD;
    const bf16* Bg = Wt + (size_t)cn * KD;

    float acc[2][NTN][4];
    #pragma unroll
    for (int mi = 0; mi < 2; ++mi)
        #pragma unroll
        for (int nt = 0; nt < NTN; ++nt)
            #pragma unroll
            for (int q = 0; q < 4; ++q) acc[mi][nt][q] = 0.f;

    auto load_stage = [&](int k0, int st) {
        bf16* Asd = As + st * BM * 40;
        bf16* Bsd = Bs + st * BN * 40;
        #pragma unroll
        for (int i = 0; i < CA; ++i) {
            int c = t + i * 256, row = c >> 2, off = (c & 3) * 8;
            cpasync16(&Asd[row * 40 + off], Ag + (size_t)row * KD + k0 + off);
        }
        #pragma unroll
        for (int i = 0; i < CB; ++i) {
            int c = t + i * 256, row = c >> 2, off = (c & 3) * 8;
            cpasync16(&Bsd[row * 40 + off], Bg + (size_t)row * KD + k0 + off);
        }
        CP_COMMIT();
    };

    load_stage(0, 0);
    load_stage(32, 1);
    for (int i = 0; i < NK; ++i) {
        int st = i % 3;
        if (i + 1 < NK) cp_wait<1>(); else cp_wait<0>();
        __syncthreads();
        if (i + 2 < NK) load_stage((i + 2) * 32, (i + 2) % 3);

        const uint32_t* A32 = (const uint32_t*)(As + st * BM * 40);
        const uint32_t* B32 = (const uint32_t*)(Bs + st * BN * 40);
        #pragma unroll
        for (int ks = 0; ks < 2; ++ks) {
            uint32_t af[2][4];
            #pragma unroll
            for (int mi = 0; mi < 2; ++mi) {
                int base = wm * 32 + mi * 16;
                af[mi][0] = A32[(base + gid    ) * 20 + ks * 8 + tig    ];
                af[mi][1] = A32[(base + gid + 8) * 20 + ks * 8 + tig    ];
                af[mi][2] = A32[(base + gid    ) * 20 + ks * 8 + tig + 4];
                af[mi][3] = A32[(base + gid + 8) * 20 + ks * 8 + tig + 4];
            }
            #pragma unroll
            for (int nt = 0; nt < NTN; ++nt) {
                int n = wn * WTN + nt * 8 + gid;
                uint32_t b0 = B32[n * 20 + ks * 8 + tig];
                uint32_t b1 = B32[n * 20 + ks * 8 + tig + 4];
                mma16(acc[0][nt], af[0][0], af[0][1], af[0][2], af[0][3], b0, b1);
                mma16(acc[1][nt], af[1][0], af[1][1], af[1][2], af[1][3], b0, b1);
            }
        }
    }
    __syncthreads();

    // ---- epilogue ----
    #pragma unroll
    for (int mi = 0; mi < 2; ++mi) {
        #pragma unroll
        for (int half = 0; half < 2; ++half) {
            int r = rm + wm * 32 + mi * 16 + gid + half * 8;
            float mrow = 0.f;
            if (MODE == 1 || MODE == 3) mrow = nm[r] ? 1.f : 0.f;
            #pragma unroll
            for (int nt = 0; nt < NTN; ++nt) {
                int c = cn + wn * WTN + nt * 8 + tig * 2;
                float bmul = (MODE == 0 && c < DIMD) ? QSCALE : 1.f;
                float v0 = acc[mi][nt][half * 2 + 0] + bias[c] * bmul;
                float v1 = acc[mi][nt][half * 2 + 1] + bias[c + 1] * bmul;
                if (MODE == 0) {
                    int part = c >> 8, hh = (c >> 5) & 7, dd = c & 31;
                    int b2 = r >> 11, n = r & 2047;
                    if (part == 2) {
                        size_t base = ((size_t)(b2 * NHEAD + hh) * HD + dd) * NSEQ + n;
                        g_vT[base]        = __float2bfloat16(v0);
                        g_vT[base + NSEQ] = __float2bfloat16(v1);
                    } else {
                        bf16* dst = (part == 0) ? g_q : g_k;
                        __nv_bfloat162 pv = __floats2bfloat162_rn(v0, v1);
                        *(__nv_bfloat162*)&dst[((size_t)(b2 * NHEAD + hh) * NSEQ + n) * HD + dd] = pv;
                    }
                } else if (MODE == 2) {
                    float g0 = 0.5f * v0 * (1.f + erff(v0 * 0.70710678118654752f));
                    float g1 = 0.5f * v1 * (1.f + erff(v1 * 0.70710678118654752f));
                    *(__nv_bfloat162*)&outb[(size_t)r * NT + c] = __floats2bfloat162_rn(g0, g1);
                } else {
                    float2 ex = *(const float2*)&extra[(size_t)r * NT + c];
                    *(float2*)&outf[(size_t)r * NT + c] =
                        make_float2(ex.x + v0 * mrow, ex.y + v1 * mrow);
                }
            }
        }
    }
}

// ---------------- bf16 MMA flash attention, register-resident P ----------------
// 8 warps; warp w owns rows w*16..+15 for BOTH QK and PV (C-frag == A-frag).
__global__ void __launch_bounds__(256, 2)
attn_mma(const float* __restrict__ ebt)
{
    extern __shared__ __align__(16) bf16 smb[];
    bf16* Qs  = smb;             // 128*40
    bf16* Ks0 = Qs  + 5120;      // 2 stages x 128*40
    bf16* Vs0 = Ks0 + 10240;     // 2 stages x 32*136
    float* tbl2 = (float*)(Vs0 + 8704);  // 16

    int tid = threadIdx.x, lane = tid & 31, warp = tid >> 5;
    int gid = lane >> 2, tig = lane & 3;
    int bid = blockIdx.x;
    int h = bid & 7, rb = (bid >> 3) & 15, b = bid >> 7;  // h fastest: code L2 reuse
    int r0 = rb * 128;
    const int bN = b * NSEQ;
    int w16 = warp * 16;

    const bf16* qptr = g_q  + ((size_t)(b * NHEAD + h) * NSEQ + r0) * HD;
    const bf16* kbh  = g_k  + (size_t)(b * NHEAD + h) * NSEQ * HD;
    const bf16* vT   = g_vT + (size_t)(b * NHEAD + h) * HD * NSEQ;

    auto load_kv = [&](int kt, int st) {
        int j0 = kt * 128;
        bf16* Ksd = Ks0 + st * 5120;
        bf16* Vsd = Vs0 + st * 4352;
        #pragma unroll
        for (int i = 0; i < 2; ++i) {
            int c = tid + i * 256, row = c >> 2, off = (c & 3) * 8;
            cpasync16(&Ksd[row * 40 + off], kbh + (size_t)(j0 + row) * HD + off);
        }
        #pragma unroll
        for (int i = 0; i < 2; ++i) {
            int c = tid + i * 256, d = c >> 4, off = (c & 15) * 8;
            cpasync16(&Vsd[d * 136 + off], vT + (size_t)d * NSEQ + j0 + off);
        }
        CP_COMMIT();
    };

    load_kv(0, 0);

    #pragma unroll
    for (int i = 0; i < 2; ++i) {
        int c = tid + i * 256, row = c >> 2, off = (c & 3) * 8;
        *(uint4*)&Qs[row * 40 + off] = *(const uint4*)(qptr + (size_t)row * HD + off);
    }
    if (tid < 16)
        tbl2[tid] = (tid == 0) ? -30000.f
                  : (tid < 10 ? ebt[(tid - 1) * NHEAD + h] * LOG2E : 0.f);
    __syncthreads();

    // Q fragments for this warp's 16 rows
    const uint32_t* Q32 = (const uint32_t*)Qs;
    uint32_t qa[2][4];
    #pragma unroll
    for (int ks = 0; ks < 2; ++ks) {
        qa[ks][0] = Q32[(w16 + gid    ) * 20 + ks * 8 + tig    ];
        qa[ks][1] = Q32[(w16 + gid + 8) * 20 + ks * 8 + tig    ];
        qa[ks][2] = Q32[(w16 + gid    ) * 20 + ks * 8 + tig + 4];
        qa[ks][3] = Q32[(w16 + gid + 8) * 20 + ks * 8 + tig + 4];
    }

    float oacc[4][4];
    #pragma unroll
    for (int nt = 0; nt < 4; ++nt)
        #pragma unroll
        for (int q = 0; q < 4; ++q) oacc[nt][q] = 0.f;
    float lp0 = 0.f, lp1 = 0.f;

    const uint8_t* crow0 = g_code + (size_t)(bN + r0 + w16 + gid    ) * NSEQ;
    const uint8_t* crow1 = g_code + (size_t)(bN + r0 + w16 + gid + 8) * NSEQ;

    for (int kt = 0; kt < 16; ++kt) {
        int st = kt & 1, j0 = kt * 128;
        cp_wait<0>();
        __syncthreads();
        if (kt + 1 < 16) load_kv(kt + 1, st ^ 1);

        // ---- QK^T: warp computes its 16 rows x full 128 cols ----
        const uint32_t* K32 = (const uint32_t*)(Ks0 + st * 5120);
        float sacc[16][4];
        #pragma unroll
        for (int nt = 0; nt < 16; ++nt)
            #pragma unroll
            for (int q = 0; q < 4; ++q) sacc[nt][q] = 0.f;
        #pragma unroll
        for (int ks = 0; ks < 2; ++ks) {
            #pragma unroll
            for (int nt = 0; nt < 16; ++nt) {
                int n = nt * 8 + gid;
                uint32_t b0 = K32[n * 20 + ks * 8 + tig];
                uint32_t b1 = K32[n * 20 + ks * 8 + tig + 4];
                mma16(sacc[nt], qa[ks][0], qa[ks][1], qa[ks][2], qa[ks][3], b0, b1);
            }
        }

        // ---- exp epilogue in registers: C-frag -> PV A-frag ----
        uint32_t pfrag[16][2];
        #pragma unroll
        for (int nt = 0; nt < 16; ++nt) {
            int coff = j0 + nt * 8 + tig * 2;
            unsigned short c0 = *(const unsigned short*)(crow0 + coff);
            unsigned short c1 = *(const unsigned short*)(crow1 + coff);
            float p00 = fexp2(sacc[nt][0] + tbl2[c0 & 0xff]);
            float p01 = fexp2(sacc[nt][1] + tbl2[c0 >> 8]);
            float p10 = fexp2(sacc[nt][2] + tbl2[c1 & 0xff]);
            float p11 = fexp2(sacc[nt][3] + tbl2[c1 >> 8]);
            lp0 += p00 + p01;
            lp1 += p10 + p11;
            __nv_bfloat162 a = __floats2bfloat162_rn(p00, p01);
            __nv_bfloat162 c = __floats2bfloat162_rn(p10, p11);
            pfrag[nt][0] = *(uint32_t*)&a;
            pfrag[nt][1] = *(uint32_t*)&c;
        }

        // ---- PV: O[16x32] += P[16x128] V[128x32], all in registers/smem ----
        const uint32_t* V32 = (const uint32_t*)(Vs0 + st * 4352);
        #pragma unroll
        for (int ks2 = 0; ks2 < 8; ++ks2) {
            uint32_t a0 = pfrag[2 * ks2    ][0];
            uint32_t a1 = pfrag[2 * ks2    ][1];
            uint32_t a2 = pfrag[2 * ks2 + 1][0];
            uint32_t a3 = pfrag[2 * ks2 + 1][1];
            #pragma unroll
            for (int nt2 = 0; nt2 < 4; ++nt2) {
                int d = nt2 * 8 + gid;
                uint32_t b0 = V32[d * 68 + ks2 * 8 + tig];
                uint32_t b1 = V32[d * 68 + ks2 * 8 + tig + 4];
                mma16(oacc[nt2], a0, a1, a2, a3, b0, b1);
            }
        }
    }

    // ---- row sums: butterfly within quad (warp owns its rows) ----
    lp0 += __shfl_xor_sync(0xffffffffu, lp0, 1);
    lp0 += __shfl_xor_sync(0xffffffffu, lp0, 2);
    lp1 += __shfl_xor_sync(0xffffffffu, lp1, 1);
    lp1 += __shfl_xor_sync(0xffffffffu, lp1, 2);
    float inv0 = lp0 > 0.f ? 1.f / lp0 : 0.f;
    float inv1 = lp1 > 0.f ? 1.f / lp1 : 0.f;

    bf16* od = g_ao + ((size_t)(bN + r0)) * DIMD + h * HD;
    #pragma unroll
    for (int nt = 0; nt < 4; ++nt) {
        int d = nt * 8 + tig * 2;
        *(__nv_bfloat162*)&od[(size_t)(w16 + gid    ) * DIMD + d] =
            __floats2bfloat162_rn(oacc[nt][0] * inv0, oacc[nt][1] * inv0);
        *(__nv_bfloat162*)&od[(size_t)(w16 + gid + 8) * DIMD + d] =
            __floats2bfloat162_rn(oacc[nt][2] * inv1, oacc[nt][3] * inv1);
    }
}

// ---------------- launch ----------------
static void* sym_addr(const void* sym)
{
    void* p = nullptr;
    cudaGetSymbolAddress(&p, sym);
    return p;
}

extern "C" void kernel_launch(void* const* d_in, const int* in_sizes, int n_in,
                              void* d_out, int out_size)
{
    const float* x      = (const float*)d_in[0];
    const int*   etyp   = (const int*)  d_in[1];
    const int*   nmask  = (const int*)  d_in[2];
    const float* qkv_w  = (const float*)d_in[3];
    const float* qkv_b  = (const float*)d_in[4];
    const float* proj_w = (const float*)d_in[5];
    const float* proj_b = (const float*)d_in[6];
    const float* ebt    = (const float*)d_in[7];
    const float* ln1_g  = (const float*)d_in[8];
    const float* ln1_b  = (const float*)d_in[9];
    const float* ln2_g  = (const float*)d_in[10];
    const float* ln2_b  = (const float*)d_in[11];
    const float* ffn_w1 = (const float*)d_in[12];
    const float* ffn_b1 = (const float*)d_in[13];
    const float* ffn_w2 = (const float*)d_in[14];
    const float* ffn_b2 = (const float*)d_in[15];
    float* out = (float*)d_out;

    bf16*  ph    = (bf16*) sym_addr(g_h);
    bf16*  pao   = (bf16*) sym_addr(g_ao);
    float* px1   = (float*)sym_addr(g_x1);
    bf16*  ph2   = (bf16*) sym_addr(g_h2);
    bf16*  pmid  = (bf16*) sym_addr(g_mid);
    bf16*  pwqkv = (bf16*) sym_addr(g_wqkv);
    bf16*  pwproj= (bf16*) sym_addr(g_wproj);
    bf16*  pwf1  = (bf16*) sym_addr(g_wf1);
    bf16*  pwf2  = (bf16*) sym_addr(g_wf2);
    uint8_t* pcode = (uint8_t*)sym_addr(g_code);

    const int ATTN_SMEM = (5120 + 10240 + 8704) * 2 + 64;        // 48192
    const int GSM_128   = 3 * (128 * 40 + 128 * 40) * 2;         // 61440
    const int GSM_64    = 3 * (64 * 40 + 64 * 40) * 2;           // 30720
    cudaFuncSetAttribute(attn_mma, cudaFuncAttributeMaxDynamicSharedMemorySize, ATTN_SMEM);
    cudaFuncSetAttribute(mma_gemm<128,128,DIMD,3*DIMD,0>, cudaFuncAttributeMaxDynamicSharedMemorySize, GSM_128);
    cudaFuncSetAttribute(mma_gemm<64,64,DIMD,DIMD,1>,     cudaFuncAttributeMaxDynamicSharedMemorySize, GSM_64);
    cudaFuncSetAttribute(mma_gemm<128,128,DIMD,FFD,2>,    cudaFuncAttributeMaxDynamicSharedMemorySize, GSM_128);
    cudaFuncSetAttribute(mma_gemm<64,64,FFD,DIMD,3>,      cudaFuncAttributeMaxDynamicSharedMemorySize, GSM_64);

    // 0) fused weight conversion + edge code precompute
    wconv_all<<<768, 256>>>(qkv_w, proj_w, ffn_w1, ffn_w2);
    edge_code_kernel<<<dim3(NSEQ, BNUM), 256>>>(etyp, nmask, pcode);

    // 1) LN1 -> bf16
    ln_kernel<<<ROWS, 256>>>(x, ln1_g, ln1_b, ph);
    // 2) QKV GEMM + scatter (q scaled; k normal; v transposed)
    mma_gemm<128, 128, DIMD, 3*DIMD, 0><<<dim3(6, 32), 256, GSM_128>>>(
        ph, pwqkv, qkv_b, nullptr, nullptr, nullptr, nullptr);
    // 3) attention
    attn_mma<<<BNUM * NHEAD * (NSEQ / 128), 256, ATTN_SMEM>>>(ebt);
    // 4) proj + residual + node mask -> x1 (fp32)
    mma_gemm<64, 64, DIMD, DIMD, 1><<<dim3(4, 64), 256, GSM_64>>>(
        pao, pwproj, proj_b, x, nmask, px1, nullptr);
    // 5) LN2 -> bf16
    ln_kernel<<<ROWS, 256>>>(px1, ln2_g, ln2_b, ph2);
    // 6) FFN1 + exact GELU -> bf16 mid
    mma_gemm<128, 128, DIMD, FFD, 2><<<dim3(8, 32), 256, GSM_128>>>(
        ph2, pwf1, ffn_b1, nullptr, nullptr, nullptr, pmid);
    // 7) FFN2 + node mask + residual -> out (fp32)
    mma_gemm<64, 64, FFD, DIMD, 3><<<dim3(4, 64), 256, GSM_64>>>(
        pmid, pwf2, ffn_b2, px1, nmask, out, nullptr);
}